// round 5
// baseline (speedup 1.0000x reference)
#include <cuda_runtime.h>
#include <cuda_bf16.h>
#include <cstdint>

// Problem constants
#define NN   50000
#define NE   100000
#define NG   2000
#define DD   300
#define DD2  600
#define NL   5
#define NT   10
#define NUM_BOND 6
#define NUM_DIR  3
#define ND   (NN*DD)
#define ED   (NE*DD)

// Padded GEMM dims
#define MPAD 50048          // 391 * 128
#define K1P  320            // K of GEMM1 (300 padded)
#define K2P  640            // K of GEMM2 (600 padded)
#define N1P  640            // N of GEMM1 (600 padded)
#define N2P  384            // N of GEMM2 (300 padded)

// ---------------- scratch ---------------------------------------------------
__device__ float g_h[ND];
__device__ float g_agg[ND];
__device__ float g_h2[ND];
__device__ __nv_bfloat16 g_Thi[(size_t)MPAD * K2P];
__device__ __nv_bfloat16 g_Tlo[(size_t)MPAD * K2P];
__device__ __nv_bfloat16 g_W1hi[NL * N1P * K1P];
__device__ __nv_bfloat16 g_W1lo[NL * N1P * K1P];
__device__ __nv_bfloat16 g_W2hi[NL * N2P * K2P];
__device__ __nv_bfloat16 g_W2lo[NL * N2P * K2P];
__device__ float g_sum[DD], g_sumsq[DD], g_mu[DD], g_rstd[DD];
__device__ float g_gsum[NG * DD], g_gcnt[NG];

// ---------------- PTX helpers (baseline ISA only) ----------------------------
__device__ __forceinline__ uint32_t smem_to_u32(const void* p) {
    uint32_t a;
    asm("{ .reg .u64 t; cvta.to.shared.u64 t, %1; cvt.u32.u64 %0, t; }" : "=r"(a) : "l"(p));
    return a;
}

#define LDMX4(r, addr) \
    asm volatile("ldmatrix.sync.aligned.m8n8.x4.shared.b16 {%0,%1,%2,%3}, [%4];" \
        : "=r"((r)[0]), "=r"((r)[1]), "=r"((r)[2]), "=r"((r)[3]) : "r"(addr))

#define MMA_BF16(d, a, b) \
    asm volatile("mma.sync.aligned.m16n8k16.row.col.f32.bf16.bf16.f32 " \
        "{%0,%1,%2,%3}, {%4,%5,%6,%7}, {%8,%9}, {%0,%1,%2,%3};" \
        : "+f"((d)[0]), "+f"((d)[1]), "+f"((d)[2]), "+f"((d)[3]) \
        : "r"((a)[0]), "r"((a)[1]), "r"((a)[2]), "r"((a)[3]), \
          "r"((b)[0]), "r"((b)[1]))

#define CP_ASYNC16(dst, src) \
    asm volatile("cp.async.ca.shared.global [%0], [%1], 16;" :: "r"(dst), "l"(src) : "memory")
#define CP_COMMIT() asm volatile("cp.async.commit_group;" ::: "memory")
#define CP_WAIT1()  asm volatile("cp.async.wait_group 1;" ::: "memory")
#define CP_WAIT0()  asm volatile("cp.async.wait_group 0;" ::: "memory")

// ---------------- elementwise / graph kernels -------------------------------

__global__ void k_init(const int* __restrict__ x,
                       const float* __restrict__ xemb1,
                       const float* __restrict__ xemb2,
                       const float* __restrict__ e1_sl,
                       const float* __restrict__ e2_sl) {
    int idx = blockIdx.x * blockDim.x + threadIdx.x;
    if (idx >= ND) return;
    int n = idx / DD, d = idx - n * DD;
    int a = x[2 * n], c = x[2 * n + 1];
    float v = xemb1[a * DD + d] + xemb2[c * DD + d];
    g_h[idx] = v;
    g_agg[idx] = v + e1_sl[d] + e2_sl[d];
}

__global__ void k_scatter(const int* __restrict__ ei,
                          const int* __restrict__ ea,
                          const float* __restrict__ e1l,
                          const float* __restrict__ e2l) {
    int idx = blockIdx.x * blockDim.x + threadIdx.x;
    if (idx >= ED) return;
    int e = idx / DD, d = idx - e * DD;
    int src = __ldg(&ei[e]);
    int dst = __ldg(&ei[NE + e]);
    int a0 = __ldg(&ea[2 * e]);
    int a1 = __ldg(&ea[2 * e + 1]);
    float msg = g_h[src * DD + d] + e1l[a0 * DD + d] + e2l[a1 * DD + d];
    atomicAdd(&g_agg[dst * DD + d], msg);
}

// split W1[l] (fp32 [300,600] row-major) -> bf16 [640,320] n-major (B^T layout)
__global__ void k_split_w1(const float* __restrict__ W1, int l) {
    int idx = blockIdx.x * blockDim.x + threadIdx.x;
    if (idx >= N1P * K1P) return;
    int n = idx / K1P, k = idx - n * K1P;
    const float* src = W1 + (size_t)l * DD * DD2;
    float v = (n < DD2 && k < DD) ? src[(size_t)k * DD2 + n] : 0.f;
    __nv_bfloat16 h = __float2bfloat16(v);
    g_W1hi[(size_t)l * N1P * K1P + idx] = h;
    g_W1lo[(size_t)l * N1P * K1P + idx] = __float2bfloat16(v - __bfloat162float(h));
}

// split W2[l] (fp32 [600,300] row-major) -> bf16 [384,640] n-major
__global__ void k_split_w2(const float* __restrict__ W2, int l) {
    int idx = blockIdx.x * blockDim.x + threadIdx.x;
    if (idx >= N2P * K2P) return;
    int n = idx / K2P, k = idx - n * K2P;
    const float* src = W2 + (size_t)l * DD2 * DD;
    float v = (n < DD && k < DD2) ? src[(size_t)k * DD + n] : 0.f;
    __nv_bfloat16 h = __float2bfloat16(v);
    g_W2hi[(size_t)l * N2P * K2P + idx] = h;
    g_W2lo[(size_t)l * N2P * K2P + idx] = __float2bfloat16(v - __bfloat162float(h));
}

// ---------------- GEMM1: persistent-A, fused fp32->bf16 split loader --------
// C = relu(g_agg[128rows, 300] @ W1[l] + b1) -> split bf16 -> g_Thi/g_Tlo.
// A panel (hi+lo, 128x320 bf16, 656B row stride) resident in smem; loops over
// 5 N-blocks of 128, streaming B in 32-k chunks (2-stage cp.async).
#define A1_RS   656
#define A1_MAT  (128*A1_RS)          // 83968
#define B1_OFF  (2*A1_MAT)           // 167936
#define B1_MAT  (128*80)             // 10240
#define G1_SMEM (B1_OFF + 4*B1_MAT)  // 208896

__global__ void __launch_bounds__(256, 1)
k_gemm1(int l, const float* __restrict__ bias) {
    const __nv_bfloat16* __restrict__ Bhi = g_W1hi + (size_t)l * N1P * K1P;
    const __nv_bfloat16* __restrict__ Blo = g_W1lo + (size_t)l * N1P * K1P;

    extern __shared__ __align__(16) char smem[];
    const uint32_t sbase = smem_to_u32(smem);
    const int tid = threadIdx.x;
    const int wid = tid >> 5;
    const int lane = tid & 31;
    const int row0 = blockIdx.x * 128;
    const int wm = wid & 1;
    const int wn = wid >> 1;
    const int lr = lane & 15;
    const int lc = lane >> 4;

    // ---- load + split A panel (fp32 g_agg -> bf16 hi/lo smem) ----
    for (int idx = tid; idx < 128 * 80; idx += 256) {
        int r = idx / 80, cg = idx - r * 80;      // cg: float4 group (0..79)
        int m = row0 + r;
        float4 v = make_float4(0.f, 0.f, 0.f, 0.f);
        if (m < NN && cg < 75) v = *(const float4*)&g_agg[(size_t)m * DD + cg * 4];
        __nv_bfloat16 h0 = __float2bfloat16(v.x), h1 = __float2bfloat16(v.y);
        __nv_bfloat16 h2 = __float2bfloat16(v.z), h3 = __float2bfloat16(v.w);
        __nv_bfloat16 l0 = __float2bfloat16(v.x - __bfloat162float(h0));
        __nv_bfloat16 l1 = __float2bfloat16(v.y - __bfloat162float(h1));
        __nv_bfloat16 l2 = __float2bfloat16(v.z - __bfloat162float(h2));
        __nv_bfloat16 l3 = __float2bfloat16(v.w - __bfloat162float(h3));
        uint32_t off = r * A1_RS + cg * 8;
        __nv_bfloat162 p;
        p.x = h0; p.y = h1; *(__nv_bfloat162*)(smem + off)              = p;
        p.x = h2; p.y = h3; *(__nv_bfloat162*)(smem + off + 4)          = p;
        p.x = l0; p.y = l1; *(__nv_bfloat162*)(smem + A1_MAT + off)     = p;
        p.x = l2; p.y = l3; *(__nv_bfloat162*)(smem + A1_MAT + off + 4) = p;
    }
    __syncthreads();

    // ---- B chunk issue: t in [0,50), nb=t/10, c=t%10 ----
    auto issueB = [&](int t) {
        const int nb = t / 10, c = t - nb * 10, buf = t & 1;
        const int col0 = nb * 128;
        #pragma unroll
        for (int i = 0; i < 4; i++) {
            int u = tid + i * 256;              // 0..1023
            int mat = u >> 9;                   // 0: hi, 1: lo
            int r = (u >> 2) & 127;
            int c16 = u & 3;
            const __nv_bfloat16* gp = (mat ? Blo : Bhi)
                + (size_t)(col0 + r) * K1P + c * 32 + c16 * 8;
            uint32_t dst = sbase + B1_OFF + buf * (2 * B1_MAT) + mat * B1_MAT
                         + r * 80 + c16 * 16;
            CP_ASYNC16(dst, gp);
        }
        CP_COMMIT();
    };

    float acc[4][4][4] = {};
    issueB(0);
    for (int t = 0; t < 50; t++) {
        const int nb = t / 10, c = t - nb * 10;
        if (t + 1 < 50) { issueB(t + 1); CP_WAIT1(); }
        else            { CP_WAIT0(); }
        __syncthreads();
        const uint32_t sbB = sbase + B1_OFF + (t & 1) * (2 * B1_MAT);
        #pragma unroll
        for (int s = 0; s < 2; s++) {
            uint32_t ahi[4][4], alo[4][4], bhi[4][2], blo[4][2];
            #pragma unroll
            for (int i = 0; i < 4; i++) {
                uint32_t ra = sbase + (wm * 64 + i * 16 + lr) * A1_RS
                            + c * 64 + s * 32 + lc * 16;
                LDMX4(ahi[i], ra);
                LDMX4(alo[i], ra + A1_MAT);
            }
            #pragma unroll
            for (int jp = 0; jp < 2; jp++) {
                uint32_t rb = sbB + (wn * 32 + jp * 16 + lr) * 80 + s * 32 + lc * 16;
                uint32_t t4[4];
                LDMX4(t4, rb);
                bhi[2 * jp][0] = t4[0]; bhi[2 * jp + 1][0] = t4[1];
                bhi[2 * jp][1] = t4[2]; bhi[2 * jp + 1][1] = t4[3];
                LDMX4(t4, rb + B1_MAT);
                blo[2 * jp][0] = t4[0]; blo[2 * jp + 1][0] = t4[1];
                blo[2 * jp][1] = t4[2]; blo[2 * jp + 1][1] = t4[3];
            }
            #pragma unroll
            for (int i = 0; i < 4; i++)
                #pragma unroll
                for (int j = 0; j < 4; j++) {
                    MMA_BF16(acc[i][j], ahi[i], bhi[j]);
                    MMA_BF16(acc[i][j], ahi[i], blo[j]);
                    MMA_BF16(acc[i][j], alo[i], bhi[j]);
                }
        }
        __syncthreads();

        if (c == 9) {  // epilogue for this N-block
            const int col0 = nb * 128;
            #pragma unroll
            for (int i = 0; i < 4; i++) {
                #pragma unroll
                for (int j = 0; j < 4; j++) {
                    #pragma unroll
                    for (int h = 0; h < 2; h++) {
                        int m = row0 + wm * 64 + i * 16 + (lane >> 2) + h * 8;
                        int n = col0 + wn * 32 + j * 8 + (lane & 3) * 2;
                        float v0 = acc[i][j][h * 2];
                        float v1 = acc[i][j][h * 2 + 1];
                        if (n < DD2) {
                            v0 = fmaxf(v0 + bias[n], 0.f);
                            v1 = fmaxf(v1 + bias[n + 1], 0.f);
                        } else { v0 = 0.f; v1 = 0.f; }
                        __nv_bfloat16 h0 = __float2bfloat16(v0);
                        __nv_bfloat16 h1 = __float2bfloat16(v1);
                        __nv_bfloat16 l0 = __float2bfloat16(v0 - __bfloat162float(h0));
                        __nv_bfloat16 l1 = __float2bfloat16(v1 - __bfloat162float(h1));
                        size_t o = (size_t)m * K2P + n;
                        __nv_bfloat162 th; th.x = h0; th.y = h1;
                        __nv_bfloat162 tl; tl.x = l0; tl.y = l1;
                        *(__nv_bfloat162*)&g_Thi[o] = th;
                        *(__nv_bfloat162*)&g_Tlo[o] = tl;
                        acc[i][j][h * 2] = 0.f;
                        acc[i][j][h * 2 + 1] = 0.f;
                    }
                }
            }
        }
    }
}

// ---------------- GEMM2: TN=192, K-streaming, fused BN statistics ------------
// g_h2 = g_T @ W2[l] + b2, plus atomic column sum / sumsq (rows < NN only).
#define A2_MAT  (128*80)             // 10240
#define B2_OFF  (4*A2_MAT)           // 40960
#define B2_MAT  (192*80)             // 15360
#define G2_SMEM (B2_OFF + 4*B2_MAT)  // 102400

__global__ void __launch_bounds__(256, 1)
k_gemm2(int l, const float* __restrict__ bias) {
    constexpr int NCHUNK = K2P / 32;   // 20
    const __nv_bfloat16* __restrict__ Bhi = g_W2hi + (size_t)l * N2P * K2P;
    const __nv_bfloat16* __restrict__ Blo = g_W2lo + (size_t)l * N2P * K2P;

    extern __shared__ __align__(16) char smem[];
    const uint32_t sbase = smem_to_u32(smem);
    const int tid = threadIdx.x;
    const int wid = tid >> 5;
    const int lane = tid & 31;
    const int row0 = blockIdx.y * 128;
    const int col0 = blockIdx.x * 192;
    const int wm = wid & 1;        // 64-row slab
    const int wn = wid >> 1;       // 48-col slab
    const int lr = lane & 15;
    const int lc = lane >> 4;

    auto issue = [&](int c) {
        const int buf = c & 1;
        const int k0 = c * 32;
        #pragma unroll
        for (int i = 0; i < 10; i++) {
            int u = tid + i * 256;              // 0..2559
            if (u < 1024) {                     // A: Thi/Tlo 128 rows
                int mat = u >> 9;
                int r = (u >> 2) & 127;
                int c16 = u & 3;
                const __nv_bfloat16* gp = (mat ? g_Tlo : g_Thi)
                    + (size_t)(row0 + r) * K2P + k0 + c16 * 8;
                uint32_t dst = sbase + buf * (2 * A2_MAT) + mat * A2_MAT
                             + r * 80 + c16 * 16;
                CP_ASYNC16(dst, gp);
            } else {                            // B: 192 rows
                int v = u - 1024;               // 0..1535
                int mat = v / 768;
                int w = v - mat * 768;
                int r = w >> 2;
                int c16 = w & 3;
                const __nv_bfloat16* gp = (mat ? Blo : Bhi)
                    + (size_t)(col0 + r) * K2P + k0 + c16 * 8;
                uint32_t dst = sbase + B2_OFF + buf * (2 * B2_MAT) + mat * B2_MAT
                             + r * 80 + c16 * 16;
                CP_ASYNC16(dst, gp);
            }
        }
        CP_COMMIT();
    };

    float acc[4][6][4] = {};

    issue(0);
    for (int c = 0; c < NCHUNK; c++) {
        if (c + 1 < NCHUNK) { issue(c + 1); CP_WAIT1(); }
        else                { CP_WAIT0(); }
        __syncthreads();
        const uint32_t sbA = sbase + (c & 1) * (2 * A2_MAT);
        const uint32_t sbB = sbase + B2_OFF + (c & 1) * (2 * B2_MAT);
        #pragma unroll
        for (int s = 0; s < 2; s++) {
            uint32_t ahi[4][4], alo[4][4], bhi[6][2], blo[6][2];
            #pragma unroll
            for (int i = 0; i < 4; i++) {
                uint32_t ra = sbA + (wm * 64 + i * 16 + lr) * 80 + s * 32 + lc * 16;
                LDMX4(ahi[i], ra);
                LDMX4(alo[i], ra + A2_MAT);
            }
            #pragma unroll
            for (int jp = 0; jp < 3; jp++) {
                uint32_t rb = sbB + (wn * 48 + jp * 16 + lr) * 80 + s * 32 + lc * 16;
                uint32_t t4[4];
                LDMX4(t4, rb);
                bhi[2 * jp][0] = t4[0]; bhi[2 * jp + 1][0] = t4[1];
                bhi[2 * jp][1] = t4[2]; bhi[2 * jp + 1][1] = t4[3];
                LDMX4(t4, rb + B2_MAT);
                blo[2 * jp][0] = t4[0]; blo[2 * jp + 1][0] = t4[1];
                blo[2 * jp][1] = t4[2]; blo[2 * jp + 1][1] = t4[3];
            }
            #pragma unroll
            for (int i = 0; i < 4; i++)
                #pragma unroll
                for (int j = 0; j < 6; j++) {
                    MMA_BF16(acc[i][j], ahi[i], bhi[j]);
                    MMA_BF16(acc[i][j], ahi[i], blo[j]);
                    MMA_BF16(acc[i][j], alo[i], bhi[j]);
                }
        }
        __syncthreads();
    }

    // epilogue: bias + write g_h2 + column stats partials
    float cs[12], cq[12];
    #pragma unroll
    for (int k = 0; k < 12; k++) { cs[k] = 0.f; cq[k] = 0.f; }

    #pragma unroll
    for (int i = 0; i < 4; i++) {
        #pragma unroll
        for (int j = 0; j < 6; j++) {
            #pragma unroll
            for (int h = 0; h < 2; h++) {
                int m = row0 + wm * 64 + i * 16 + (lane >> 2) + h * 8;
                int n = col0 + wn * 48 + j * 8 + (lane & 3) * 2;
                if (m < NN && n < DD) {
                    float v0 = acc[i][j][h * 2]     + bias[n];
                    float v1 = acc[i][j][h * 2 + 1] + bias[n + 1];
                    float2 v; v.x = v0; v.y = v1;
                    *(float2*)&g_h2[(size_t)m * DD + n] = v;
                    cs[j * 2]     += v0; cq[j * 2]     += v0 * v0;
                    cs[j * 2 + 1] += v1; cq[j * 2 + 1] += v1 * v1;
                }
            }
        }
    }
    // reduce over lane bits 2..4 (row groups within the warp slab)
    #pragma unroll
    for (int off = 4; off < 32; off <<= 1) {
        #pragma unroll
        for (int k = 0; k < 12; k++) {
            cs[k] += __shfl_xor_sync(0xffffffffu, cs[k], off);
            cq[k] += __shfl_xor_sync(0xffffffffu, cq[k], off);
        }
    }
    if ((lane >> 2) == 0) {
        #pragma unroll
        for (int k = 0; k < 12; k++) {
            int n = col0 + wn * 48 + (k >> 1) * 8 + (lane & 3) * 2 + (k & 1);
            if (n < DD) {
                atomicAdd(&g_sum[n], cs[k]);
                atomicAdd(&g_sumsq[n], cq[k]);
            }
        }
    }
}

// ---------------- BN / pool / pred ------------------------------------------

__global__ void k_zero_stats() {
    int t = threadIdx.x;
    if (t < DD) { g_sum[t] = 0.f; g_sumsq[t] = 0.f; }
}

__global__ void k_finstats() {
    int d = threadIdx.x;
    if (d < DD) {
        float mu = g_sum[d] * (1.0f / NN);
        float var = g_sumsq[d] * (1.0f / NN) - mu * mu;
        g_mu[d] = mu;
        g_rstd[d] = rsqrtf(var + 1e-5f);
    }
}

// BN apply; mode 0: g_h = relu(v), g_agg = relu(v)+sl; mode 1: extOut = v
__global__ void k_bn(const float* __restrict__ gamma_l,
                     const float* __restrict__ beta_l,
                     const float* __restrict__ e1_sl,
                     const float* __restrict__ e2_sl,
                     float* __restrict__ extOut, int mode) {
    int idx = blockIdx.x * blockDim.x + threadIdx.x;
    if (idx >= ND) return;
    int d = idx % DD;
    float v = (g_h2[idx] - g_mu[d]) * g_rstd[d] * gamma_l[d] + beta_l[d];
    if (mode == 0) {
        float r = fmaxf(v, 0.f);
        g_h[idx] = r;
        g_agg[idx] = r + e1_sl[d] + e2_sl[d];
    } else {
        extOut[idx] = v;
    }
}

__global__ void k_zero_pool() {
    int idx = blockIdx.x * blockDim.x + threadIdx.x;
    if (idx < NG * DD) g_gsum[idx] = 0.f;
    if (idx < NG) g_gcnt[idx] = 0.f;
}

__global__ void k_pool(const int* __restrict__ batch,
                       const float* __restrict__ rep) {
    int idx = blockIdx.x * blockDim.x + threadIdx.x;
    if (idx >= ND) return;
    int n = idx / DD, d = idx - n * DD;
    int b = batch[n];
    atomicAdd(&g_gsum[b * DD + d], rep[idx]);
    if (d == 0) atomicAdd(&g_gcnt[b], 1.0f);
}

__global__ void k_pred(const float* __restrict__ predW,
                       const float* __restrict__ predb,
                       float* __restrict__ grep_out,
                       float* __restrict__ pred_out) {
    int g = blockIdx.x;
    __shared__ float rep[DD];
    float inv = 1.0f / fmaxf(g_gcnt[g], 1.0f);
    for (int d = threadIdx.x; d < DD; d += blockDim.x) {
        float v = g_gsum[g * DD + d] * inv;
        rep[d] = v;
        grep_out[g * DD + d] = v;
    }
    __syncthreads();
    if (threadIdx.x < NT) {
        int t = threadIdx.x;
        float acc = predb[t];
        for (int d = 0; d < DD; ++d) acc += rep[d] * predW[d * NT + t];
        pred_out[g * NT + t] = acc;
    }
}

// ---------------- host orchestration ---------------------------------------

static void run_gnn(const int* x, const int* ei, const int* ea, const int* batch,
                    const float* xemb1, const float* xemb2,
                    const float* eemb1, const float* eemb2,
                    const float* b1, const float* b2,
                    const float* gamma, const float* beta,
                    const float* predW, const float* predb,
                    float* pred_out, float* grep_out, float* nrep_out) {
    const int BLK = 256;
    const int GRID_ND = (ND + BLK - 1) / BLK;
    const int GRID_ED = (ED + BLK - 1) / BLK;
    const int GRID_M = MPAD / 128;  // 391

    k_init<<<GRID_ND, BLK>>>(x, xemb1, xemb2, eemb1 + 4 * DD, eemb2);

    for (int l = 0; l < NL; ++l) {
        const float* e1l = eemb1 + (size_t)l * NUM_BOND * DD;
        const float* e2l = eemb2 + (size_t)l * NUM_DIR * DD;

        k_scatter<<<GRID_ED, BLK>>>(ei, ea, e1l, e2l);
        k_zero_stats<<<1, 384>>>();

        k_gemm1<<<GRID_M, 256, G1_SMEM>>>(l, b1 + (size_t)l * DD2);
        k_gemm2<<<dim3(2, GRID_M), 256, G2_SMEM>>>(l, b2 + (size_t)l * DD);

        k_finstats<<<1, 384>>>();

        int last = (l == NL - 1);
        const float* e1n = eemb1 + (size_t)(last ? l : l + 1) * NUM_BOND * DD;
        const float* e2n = eemb2 + (size_t)(last ? l : l + 1) * NUM_DIR * DD;
        k_bn<<<GRID_ND, BLK>>>(gamma + (size_t)l * DD, beta + (size_t)l * DD,
                               e1n + 4 * DD, e2n, nrep_out, last);
    }

    k_zero_pool<<<(NG * DD + BLK - 1) / BLK, BLK>>>();
    k_pool<<<GRID_ND, BLK>>>(batch, nrep_out);
    k_pred<<<NG, 128>>>(predW, predb, grep_out, pred_out);
}

extern "C" void kernel_launch(void* const* d_in, const int* in_sizes, int n_in,
                              void* d_out, int out_size) {
    const int*   x      = (const int*)d_in[0];
    const int*   ei     = (const int*)d_in[1];
    const int*   ea     = (const int*)d_in[2];
    const int*   batch  = (const int*)d_in[3];
    const int*   x1     = (const int*)d_in[4];
    const int*   ei1    = (const int*)d_in[5];
    const int*   ea1    = (const int*)d_in[6];
    const int*   batch1 = (const int*)d_in[7];
    const float* xemb1  = (const float*)d_in[8];
    const float* xemb2  = (const float*)d_in[9];
    const float* eemb1  = (const float*)d_in[10];
    const float* eemb2  = (const float*)d_in[11];
    const float* W1     = (const float*)d_in[12];
    const float* b1     = (const float*)d_in[13];
    const float* W2     = (const float*)d_in[14];
    const float* b2     = (const float*)d_in[15];
    const float* gamma  = (const float*)d_in[16];
    const float* beta   = (const float*)d_in[17];
    const float* predW  = (const float*)d_in[18];
    const float* predb  = (const float*)d_in[19];

    cudaFuncSetAttribute(k_gemm1, cudaFuncAttributeMaxDynamicSharedMemorySize, G1_SMEM);
    cudaFuncSetAttribute(k_gemm2, cudaFuncAttributeMaxDynamicSharedMemorySize, G2_SMEM);

    for (int l = 0; l < NL; ++l) {
        k_split_w1<<<(N1P * K1P + 255) / 256, 256>>>(W1, l);
        k_split_w2<<<(N2P * K2P + 255) / 256, 256>>>(W2, l);
    }

    float* out = (float*)d_out;
    float* pred0 = out;
    float* grep0 = out + NG * NT;
    float* nrep0 = out + NG * NT + NG * DD;
    float* pred1 = out + NG * NT + NG * DD + (size_t)NN * DD;
    float* grep1 = pred1 + NG * NT;
    float* nrep1 = pred1 + NG * NT + NG * DD;

    run_gnn(x,  ei,  ea,  batch,  xemb1, xemb2, eemb1, eemb2,
            b1, b2, gamma, beta, predW, predb, pred0, grep0, nrep0);
    run_gnn(x1, ei1, ea1, batch1, xemb1, xemb2, eemb1, eemb2,
            b1, b2, gamma, beta, predW, predb, pred1, grep1, nrep1);
}

// round 6
// speedup vs baseline: 1.2054x; 1.2054x over previous
#include <cuda_runtime.h>
#include <cuda_bf16.h>
#include <cstdint>

// Problem constants
#define NN   50000
#define NE   100000
#define NG   2000
#define DD   300
#define DD2  600
#define NL   5
#define NT   10
#define NUM_BOND 6
#define NUM_DIR  3
#define ND   (NN*DD)
#define ED   (NE*DD)

// Padded GEMM dims (per graph), both graphs stacked along M
#define MPAD  50048          // 391 * 128
#define M2PAD (2*MPAD)       // 100096, 782 blocks of 128
#define K1P  320
#define K2P  640
#define N1P  640
#define N2P  384

// smem tile geometry: 128 rows x 32 bf16, padded to 80B row stride
#define RS     80
#define MATB   (128*RS)
#define STAGEB (4*MATB)
#define MG_SMEM (2*STAGEB)     // 81920

// ---------------- scratch ---------------------------------------------------
__device__ float g_h[2*ND];
__device__ float g_agg[2*ND];
__device__ float g_h2[2*ND];
__device__ __nv_bfloat16 g_Ahi[(size_t)M2PAD * K1P];
__device__ __nv_bfloat16 g_Alo[(size_t)M2PAD * K1P];
__device__ __nv_bfloat16 g_Thi[(size_t)M2PAD * K2P];
__device__ __nv_bfloat16 g_Tlo[(size_t)M2PAD * K2P];
__device__ __nv_bfloat16 g_W1hi[NL * N1P * K1P];
__device__ __nv_bfloat16 g_W1lo[NL * N1P * K1P];
__device__ __nv_bfloat16 g_W2hi[NL * N2P * K2P];
__device__ __nv_bfloat16 g_W2lo[NL * N2P * K2P];
__device__ float g_sum[2*DD], g_sumsq[2*DD];
__device__ float g_gsum[2*NG*DD], g_gcnt[2*NG];

// ---------------- PTX helpers (baseline ISA only) ----------------------------
__device__ __forceinline__ uint32_t smem_to_u32(const void* p) {
    uint32_t a;
    asm("{ .reg .u64 t; cvta.to.shared.u64 t, %1; cvt.u32.u64 %0, t; }" : "=r"(a) : "l"(p));
    return a;
}

#define LDMX4(r, addr) \
    asm volatile("ldmatrix.sync.aligned.m8n8.x4.shared.b16 {%0,%1,%2,%3}, [%4];" \
        : "=r"((r)[0]), "=r"((r)[1]), "=r"((r)[2]), "=r"((r)[3]) : "r"(addr))

#define MMA_BF16(d, a, b) \
    asm volatile("mma.sync.aligned.m16n8k16.row.col.f32.bf16.bf16.f32 " \
        "{%0,%1,%2,%3}, {%4,%5,%6,%7}, {%8,%9}, {%0,%1,%2,%3};" \
        : "+f"((d)[0]), "+f"((d)[1]), "+f"((d)[2]), "+f"((d)[3]) \
        : "r"((a)[0]), "r"((a)[1]), "r"((a)[2]), "r"((a)[3]), \
          "r"((b)[0]), "r"((b)[1]))

#define CP_ASYNC16(dst, src) \
    asm volatile("cp.async.ca.shared.global [%0], [%1], 16;" :: "r"(dst), "l"(src) : "memory")
#define CP_COMMIT() asm volatile("cp.async.commit_group;" ::: "memory")
#define CP_WAIT1()  asm volatile("cp.async.wait_group 1;" ::: "memory")
#define CP_WAIT0()  asm volatile("cp.async.wait_group 0;" ::: "memory")

// ---------------- elementwise / graph kernels (both graphs batched) ----------

// init h + self-loop agg for both graphs; also zeroes pool accumulators
__global__ void k_init(const int* __restrict__ x0, const int* __restrict__ x1,
                       const float* __restrict__ xemb1,
                       const float* __restrict__ xemb2,
                       const float* __restrict__ e1_sl,
                       const float* __restrict__ e2_sl) {
    int idx = blockIdx.x * blockDim.x + threadIdx.x;
    if (idx < 2 * NG * DD) g_gsum[idx] = 0.f;
    if (idx < 2 * NG) g_gcnt[idx] = 0.f;
    if (idx >= 2 * ND) return;
    int gi = idx >= ND;
    int loc = idx - gi * ND;
    int n = loc / DD, d = loc - n * DD;
    const int* xs = gi ? x1 : x0;
    int a = xs[2 * n], c = xs[2 * n + 1];
    float v = xemb1[a * DD + d] + xemb2[c * DD + d];
    g_h[idx] = v;
    g_agg[idx] = v + e1_sl[d] + e2_sl[d];
}

__global__ void k_scatter(const int* __restrict__ ei0, const int* __restrict__ ea0,
                          const int* __restrict__ ei1, const int* __restrict__ ea1,
                          const float* __restrict__ e1l,
                          const float* __restrict__ e2l) {
    int idx = blockIdx.x * blockDim.x + threadIdx.x;
    if (idx >= 2 * ED) return;
    int gi = idx >= ED;
    int loc = idx - gi * ED;
    int e = loc / DD, d = loc - e * DD;
    const int* eis = gi ? ei1 : ei0;
    const int* eas = gi ? ea1 : ea0;
    int src = __ldg(&eis[e]);
    int dst = __ldg(&eis[NE + e]);
    int a0 = __ldg(&eas[2 * e]);
    int a1 = __ldg(&eas[2 * e + 1]);
    size_t base = (size_t)gi * ND;
    float msg = g_h[base + (size_t)src * DD + d] + e1l[a0 * DD + d] + e2l[a1 * DD + d];
    atomicAdd(&g_agg[base + (size_t)dst * DD + d], msg);
}

// split g_agg (both graphs) -> g_Ahi/g_Alo [M2PAD,320]; block 0 zeroes stats
__global__ void k_split_agg() {
    int idx = blockIdx.x * blockDim.x + threadIdx.x;
    if (blockIdx.x == 0) {
        for (int t = threadIdx.x; t < 2 * DD; t += blockDim.x) {
            g_sum[t] = 0.f; g_sumsq[t] = 0.f;
        }
    }
    if (idx >= M2PAD * (K1P / 2)) return;
    int m = idx / (K1P / 2);
    int k = (idx - m * (K1P / 2)) * 2;
    int gi = m >= MPAD;
    int node = m - gi * MPAD;
    float v0 = 0.f, v1 = 0.f;
    if (node < NN && k < DD) {
        const float* p = g_agg + (size_t)gi * ND + (size_t)node * DD + k;
        v0 = p[0]; v1 = p[1];
    }
    __nv_bfloat16 h0 = __float2bfloat16(v0);
    __nv_bfloat16 h1 = __float2bfloat16(v1);
    __nv_bfloat16 l0 = __float2bfloat16(v0 - __bfloat162float(h0));
    __nv_bfloat16 l1 = __float2bfloat16(v1 - __bfloat162float(h1));
    size_t o = (size_t)m * K1P + k;
    __nv_bfloat162 th; th.x = h0; th.y = h1;
    __nv_bfloat162 tl; tl.x = l0; tl.y = l1;
    *(__nv_bfloat162*)&g_Ahi[o] = th;
    *(__nv_bfloat162*)&g_Alo[o] = tl;
}

// weight splits (once per call, shared by both graphs)
__global__ void k_split_w1(const float* __restrict__ W1, int l) {
    int idx = blockIdx.x * blockDim.x + threadIdx.x;
    if (idx >= N1P * K1P) return;
    int n = idx / K1P, k = idx - n * K1P;
    const float* src = W1 + (size_t)l * DD * DD2;
    float v = (n < DD2 && k < DD) ? src[(size_t)k * DD2 + n] : 0.f;
    __nv_bfloat16 h = __float2bfloat16(v);
    g_W1hi[(size_t)l * N1P * K1P + idx] = h;
    g_W1lo[(size_t)l * N1P * K1P + idx] = __float2bfloat16(v - __bfloat162float(h));
}

__global__ void k_split_w2(const float* __restrict__ W2, int l) {
    int idx = blockIdx.x * blockDim.x + threadIdx.x;
    if (idx >= N2P * K2P) return;
    int n = idx / K2P, k = idx - n * K2P;
    const float* src = W2 + (size_t)l * DD2 * DD;
    float v = (n < DD && k < DD2) ? src[(size_t)k * DD + n] : 0.f;
    __nv_bfloat16 h = __float2bfloat16(v);
    g_W2hi[(size_t)l * N2P * K2P + idx] = h;
    g_W2lo[(size_t)l * N2P * K2P + idx] = __float2bfloat16(v - __bfloat162float(h));
}

// ---------------- mma.sync bf16-split GEMM (R4-proven mainloop) -------------
// MODE 0: relu(Ahi/Alo @ W1 + b1) -> split bf16 -> g_Thi/g_Tlo
// MODE 1: T @ W2 + b2 -> fp32 g_h2 (+ fused per-graph BN column stats)
template <int MODE>
__global__ void __launch_bounds__(256)
k_mgemm(int l, const float* __restrict__ bias) {
    constexpr int KPAD = MODE ? K2P : K1P;
    constexpr int NC   = MODE ? DD  : DD2;
    constexpr int NCHUNK = KPAD / 32;
    const __nv_bfloat16* __restrict__ Ahi = MODE ? g_Thi : g_Ahi;
    const __nv_bfloat16* __restrict__ Alo = MODE ? g_Tlo : g_Alo;
    const __nv_bfloat16* __restrict__ Bhi =
        MODE ? (g_W2hi + (size_t)l * N2P * K2P) : (g_W1hi + (size_t)l * N1P * K1P);
    const __nv_bfloat16* __restrict__ Blo =
        MODE ? (g_W2lo + (size_t)l * N2P * K2P) : (g_W1lo + (size_t)l * N1P * K1P);

    extern __shared__ __align__(16) char smem[];
    const uint32_t sbase = smem_to_u32(smem);
    const int tid = threadIdx.x;
    const int wid = tid >> 5;
    const int lane = tid & 31;
    const int row0 = blockIdx.y * 128;
    const int col0 = blockIdx.x * 128;
    const int wm = wid & 1;
    const int wn = wid >> 1;
    const int lr = lane & 15;
    const int lc = lane >> 4;

    auto issue = [&](int c) {
        const int buf = c & 1;
        const int k0 = c * 32;
        #pragma unroll
        for (int i = 0; i < 8; i++) {
            int u = tid + i * 256;
            int mat = u >> 9;
            int r = (u >> 2) & 127;
            int c16 = u & 3;
            const __nv_bfloat16* gp;
            if (mat == 0)      gp = Ahi + (size_t)(row0 + r) * KPAD;
            else if (mat == 1) gp = Alo + (size_t)(row0 + r) * KPAD;
            else if (mat == 2) gp = Bhi + (size_t)(col0 + r) * KPAD;
            else               gp = Blo + (size_t)(col0 + r) * KPAD;
            gp += k0 + c16 * 8;
            uint32_t dst = sbase + buf * STAGEB + mat * MATB + r * RS + c16 * 16;
            CP_ASYNC16(dst, gp);
        }
        CP_COMMIT();
    };

    float acc[4][4][4] = {};

    issue(0);
    for (int c = 0; c < NCHUNK; c++) {
        if (c + 1 < NCHUNK) { issue(c + 1); CP_WAIT1(); }
        else                { CP_WAIT0(); }
        __syncthreads();
        const uint32_t sb = sbase + (c & 1) * STAGEB;
        #pragma unroll
        for (int s = 0; s < 2; s++) {
            uint32_t ahi[4][4], alo[4][4], bhi[4][2], blo[4][2];
            #pragma unroll
            for (int i = 0; i < 4; i++) {
                uint32_t ra = sb + (wm * 64 + i * 16 + lr) * RS + s * 32 + lc * 16;
                LDMX4(ahi[i], ra);
                LDMX4(alo[i], ra + MATB);
            }
            #pragma unroll
            for (int jp = 0; jp < 2; jp++) {
                uint32_t rb = sb + 2 * MATB + (wn * 32 + jp * 16 + lr) * RS + s * 32 + lc * 16;
                uint32_t t[4];
                LDMX4(t, rb);
                bhi[2 * jp][0] = t[0]; bhi[2 * jp + 1][0] = t[1];
                bhi[2 * jp][1] = t[2]; bhi[2 * jp + 1][1] = t[3];
                LDMX4(t, rb + MATB);
                blo[2 * jp][0] = t[0]; blo[2 * jp + 1][0] = t[1];
                blo[2 * jp][1] = t[2]; blo[2 * jp + 1][1] = t[3];
            }
            #pragma unroll
            for (int i = 0; i < 4; i++)
                #pragma unroll
                for (int j = 0; j < 4; j++) {
                    MMA_BF16(acc[i][j], ahi[i], bhi[j]);
                    MMA_BF16(acc[i][j], ahi[i], blo[j]);
                    MMA_BF16(acc[i][j], alo[i], bhi[j]);
                }
        }
        __syncthreads();
    }

    if (MODE == 0) {
        #pragma unroll
        for (int i = 0; i < 4; i++) {
            #pragma unroll
            for (int j = 0; j < 4; j++) {
                #pragma unroll
                for (int h = 0; h < 2; h++) {
                    int m = row0 + wm * 64 + i * 16 + (lane >> 2) + h * 8;
                    int n = col0 + wn * 32 + j * 8 + (lane & 3) * 2;
                    float v0 = acc[i][j][h * 2];
                    float v1 = acc[i][j][h * 2 + 1];
                    if (n < NC) {
                        v0 = fmaxf(v0 + bias[n], 0.f);
                        v1 = fmaxf(v1 + bias[n + 1], 0.f);
                    } else { v0 = 0.f; v1 = 0.f; }
                    __nv_bfloat16 h0 = __float2bfloat16(v0);
                    __nv_bfloat16 h1 = __float2bfloat16(v1);
                    __nv_bfloat16 l0 = __float2bfloat16(v0 - __bfloat162float(h0));
                    __nv_bfloat16 l1 = __float2bfloat16(v1 - __bfloat162float(h1));
                    size_t o = (size_t)m * K2P + n;
                    __nv_bfloat162 th; th.x = h0; th.y = h1;
                    __nv_bfloat162 tl; tl.x = l0; tl.y = l1;
                    *(__nv_bfloat162*)&g_Thi[o] = th;
                    *(__nv_bfloat162*)&g_Tlo[o] = tl;
                }
            }
        }
    } else {
        // epilogue: bias + write g_h2 + per-graph column stats
        const int gi = row0 >= MPAD;              // block never straddles graphs
        float cs[8], cq[8];
        #pragma unroll
        for (int k = 0; k < 8; k++) { cs[k] = 0.f; cq[k] = 0.f; }
        #pragma unroll
        for (int i = 0; i < 4; i++) {
            #pragma unroll
            for (int j = 0; j < 4; j++) {
                #pragma unroll
                for (int h = 0; h < 2; h++) {
                    int m = row0 + wm * 64 + i * 16 + (lane >> 2) + h * 8;
                    int node = m - gi * MPAD;
                    int n = col0 + wn * 32 + j * 8 + (lane & 3) * 2;
                    if (node < NN && n < NC) {
                        float v0 = acc[i][j][h * 2]     + bias[n];
                        float v1 = acc[i][j][h * 2 + 1] + bias[n + 1];
                        float2 v; v.x = v0; v.y = v1;
                        *(float2*)&g_h2[((size_t)gi * NN + node) * DD + n] = v;
                        cs[j * 2]     += v0; cq[j * 2]     += v0 * v0;
                        cs[j * 2 + 1] += v1; cq[j * 2 + 1] += v1 * v1;
                    }
                }
            }
        }
        #pragma unroll
        for (int off = 4; off < 32; off <<= 1) {
            #pragma unroll
            for (int k = 0; k < 8; k++) {
                cs[k] += __shfl_xor_sync(0xffffffffu, cs[k], off);
                cq[k] += __shfl_xor_sync(0xffffffffu, cq[k], off);
            }
        }
        if ((lane >> 2) == 0) {
            #pragma unroll
            for (int k = 0; k < 8; k++) {
                int n = col0 + wn * 32 + (k >> 1) * 8 + (lane & 3) * 2 + (k & 1);
                if (n < NC) {
                    atomicAdd(&g_sum[gi * DD + n], cs[k]);
                    atomicAdd(&g_sumsq[gi * DD + n], cq[k]);
                }
            }
        }
    }
}

// ---------------- BN / pool / pred ------------------------------------------

// BN apply (both graphs); mode 0: g_h=relu(v), g_agg=relu(v)+sl; mode 1: node_rep out
__global__ void k_bn(const float* __restrict__ gamma_l,
                     const float* __restrict__ beta_l,
                     const float* __restrict__ e1_sl,
                     const float* __restrict__ e2_sl,
                     float* __restrict__ nrep0,
                     float* __restrict__ nrep1, int mode) {
    int idx = blockIdx.x * blockDim.x + threadIdx.x;
    if (idx >= 2 * ND) return;
    int gi = idx >= ND;
    int loc = idx - gi * ND;
    int d = loc % DD;
    float s = g_sum[gi * DD + d];
    float q = g_sumsq[gi * DD + d];
    float mu = s * (1.0f / NN);
    float var = q * (1.0f / NN) - mu * mu;
    float rstd = rsqrtf(var + 1e-5f);
    float v = (g_h2[idx] - mu) * rstd * gamma_l[d] + beta_l[d];
    if (mode == 0) {
        float r = fmaxf(v, 0.f);
        g_h[idx] = r;
        g_agg[idx] = r + e1_sl[d] + e2_sl[d];
    } else {
        (gi ? nrep1 : nrep0)[loc] = v;
    }
}

__global__ void k_pool(const int* __restrict__ batch0,
                       const int* __restrict__ batch1,
                       const float* __restrict__ nrep0,
                       const float* __restrict__ nrep1) {
    int idx = blockIdx.x * blockDim.x + threadIdx.x;
    if (idx >= 2 * ND) return;
    int gi = idx >= ND;
    int loc = idx - gi * ND;
    int n = loc / DD, d = loc - n * DD;
    int b = (gi ? batch1 : batch0)[n];
    float v = (gi ? nrep1 : nrep0)[loc];
    atomicAdd(&g_gsum[((size_t)gi * NG + b) * DD + d], v);
    if (d == 0) atomicAdd(&g_gcnt[gi * NG + b], 1.0f);
}

__global__ void k_pred(const float* __restrict__ predW,
                       const float* __restrict__ predb,
                       float* __restrict__ grep0, float* __restrict__ pred0,
                       float* __restrict__ grep1, float* __restrict__ pred1) {
    int g = blockIdx.x;           // 0 .. 2*NG-1
    int gi = g >= NG;
    int gl = g - gi * NG;
    float* grep = gi ? grep1 : grep0;
    float* pred = gi ? pred1 : pred0;
    __shared__ float rep[DD];
    float inv = 1.0f / fmaxf(g_gcnt[g], 1.0f);
    for (int d = threadIdx.x; d < DD; d += blockDim.x) {
        float v = g_gsum[(size_t)g * DD + d] * inv;
        rep[d] = v;
        grep[gl * DD + d] = v;
    }
    __syncthreads();
    if (threadIdx.x < NT) {
        int t = threadIdx.x;
        float acc = predb[t];
        for (int d = 0; d < DD; ++d) acc += rep[d] * predW[d * NT + t];
        pred[gl * NT + t] = acc;
    }
}

// ---------------- host orchestration ---------------------------------------

extern "C" void kernel_launch(void* const* d_in, const int* in_sizes, int n_in,
                              void* d_out, int out_size) {
    const int*   x      = (const int*)d_in[0];
    const int*   ei     = (const int*)d_in[1];
    const int*   ea     = (const int*)d_in[2];
    const int*   batch  = (const int*)d_in[3];
    const int*   x1     = (const int*)d_in[4];
    const int*   ei1    = (const int*)d_in[5];
    const int*   ea1    = (const int*)d_in[6];
    const int*   batch1 = (const int*)d_in[7];
    const float* xemb1  = (const float*)d_in[8];
    const float* xemb2  = (const float*)d_in[9];
    const float* eemb1  = (const float*)d_in[10];
    const float* eemb2  = (const float*)d_in[11];
    const float* W1     = (const float*)d_in[12];
    const float* b1     = (const float*)d_in[13];
    const float* W2     = (const float*)d_in[14];
    const float* b2     = (const float*)d_in[15];
    const float* gamma  = (const float*)d_in[16];
    const float* beta   = (const float*)d_in[17];
    const float* predW  = (const float*)d_in[18];
    const float* predb  = (const float*)d_in[19];

    cudaFuncSetAttribute(k_mgemm<0>, cudaFuncAttributeMaxDynamicSharedMemorySize, MG_SMEM);
    cudaFuncSetAttribute(k_mgemm<1>, cudaFuncAttributeMaxDynamicSharedMemorySize, MG_SMEM);

    float* out = (float*)d_out;
    float* pred0 = out;
    float* grep0 = out + NG * NT;
    float* nrep0 = out + NG * NT + NG * DD;
    float* pred1 = out + NG * NT + NG * DD + (size_t)NN * DD;
    float* grep1 = pred1 + NG * NT;
    float* nrep1 = pred1 + NG * NT + NG * DD;

    const int BLK = 256;
    const int GRID_2ND = (2 * ND + BLK - 1) / BLK;
    const int GRID_2ED = (2 * ED + BLK - 1) / BLK;
    const int GRID_M2 = M2PAD / 128;  // 782
    const int GRID_SPLIT = (M2PAD * (K1P / 2) + BLK - 1) / BLK;

    for (int l = 0; l < NL; ++l) {
        k_split_w1<<<(N1P * K1P + 255) / 256, 256>>>(W1, l);
        k_split_w2<<<(N2P * K2P + 255) / 256, 256>>>(W2, l);
    }

    k_init<<<GRID_2ND, BLK>>>(x, x1, xemb1, xemb2, eemb1 + 4 * DD, eemb2);

    for (int l = 0; l < NL; ++l) {
        const float* e1l = eemb1 + (size_t)l * NUM_BOND * DD;
        const float* e2l = eemb2 + (size_t)l * NUM_DIR * DD;

        k_scatter<<<GRID_2ED, BLK>>>(ei, ea, ei1, ea1, e1l, e2l);
        k_split_agg<<<GRID_SPLIT, BLK>>>();

        k_mgemm<0><<<dim3(N1P / 128, GRID_M2), 256, MG_SMEM>>>(l, b1 + (size_t)l * DD2);
        k_mgemm<1><<<dim3(N2P / 128, GRID_M2), 256, MG_SMEM>>>(l, b2 + (size_t)l * DD);

        int last = (l == NL - 1);
        const float* e1n = eemb1 + (size_t)(last ? l : l + 1) * NUM_BOND * DD;
        const float* e2n = eemb2 + (size_t)(last ? l : l + 1) * NUM_DIR * DD;
        k_bn<<<GRID_2ND, BLK>>>(gamma + (size_t)l * DD, beta + (size_t)l * DD,
                                e1n + 4 * DD, e2n, nrep0, nrep1, last);
    }

    k_pool<<<GRID_2ND, BLK>>>(batch, batch1, nrep0, nrep1);
    k_pred<<<2 * NG, 128>>>(predW, predb, grep0, pred0, grep1, pred1);
}

// round 8
// speedup vs baseline: 1.2599x; 1.0453x over previous
#include <cuda_runtime.h>
#include <cuda_bf16.h>
#include <cstdint>

// Problem constants
#define NN   50000
#define NE   100000
#define NG   2000
#define DD   300
#define DD2  600
#define NL   5
#define NT   10
#define NUM_BOND 6
#define NUM_DIR  3
#define ND   (NN*DD)
#define ED   (NE*DD)

// Padded GEMM dims (per graph), both graphs stacked along M
#define MPAD  50048          // 391 * 128
#define M2PAD (2*MPAD)       // 100096, 782 row blocks
#define K1P  320             // GEMM1 K (300 padded), 10 chunks
#define K2P  608             // GEMM2 K / T row stride (600 padded), 19 chunks
#define N1P  640             // GEMM1 N sweep (600 real; stores guarded to <608)
#define N2P  320             // GEMM2 N (300 padded): 128+128+64 blocks

// smem geometry: A tiles 128 rows x 32 bf16, 80B row stride; B tiles TN rows
#define RS     80
#define MATB   (128*RS)                      // 10240 per A matrix tile

// ---------------- scratch ---------------------------------------------------
__device__ float g_h[2*ND];
__device__ float g_agg[2*ND];
__device__ float g_h2[2*ND];
__device__ __nv_bfloat16 g_Ahi[(size_t)M2PAD * K1P];
__device__ __nv_bfloat16 g_Alo[(size_t)M2PAD * K1P];
__device__ __nv_bfloat16 g_Thi[(size_t)M2PAD * K2P];
__device__ __nv_bfloat16 g_Tlo[(size_t)M2PAD * K2P];
__device__ __nv_bfloat16 g_W1hi[NL * N1P * K1P];
__device__ __nv_bfloat16 g_W1lo[NL * N1P * K1P];
__device__ __nv_bfloat16 g_W2hi[NL * N2P * K2P];
__device__ __nv_bfloat16 g_W2lo[NL * N2P * K2P];
__device__ float g_sum[2*DD], g_sumsq[2*DD];
__device__ float g_gsum[2*NG*DD], g_gcnt[2*NG];

// ---------------- PTX helpers (baseline ISA only) ----------------------------
__device__ __forceinline__ uint32_t smem_to_u32(const void* p) {
    uint32_t a;
    asm("{ .reg .u64 t; cvta.to.shared.u64 t, %1; cvt.u32.u64 %0, t; }" : "=r"(a) : "l"(p));
    return a;
}

#define LDMX4(r, addr) \
    asm volatile("ldmatrix.sync.aligned.m8n8.x4.shared.b16 {%0,%1,%2,%3}, [%4];" \
        : "=r"((r)[0]), "=r"((r)[1]), "=r"((r)[2]), "=r"((r)[3]) : "r"(addr))

#define MMA_BF16(d, a, b) \
    asm volatile("mma.sync.aligned.m16n8k16.row.col.f32.bf16.bf16.f32 " \
        "{%0,%1,%2,%3}, {%4,%5,%6,%7}, {%8,%9}, {%0,%1,%2,%3};" \
        : "+f"((d)[0]), "+f"((d)[1]), "+f"((d)[2]), "+f"((d)[3]) \
        : "r"((a)[0]), "r"((a)[1]), "r"((a)[2]), "r"((a)[3]), \
          "r"((b)[0]), "r"((b)[1]))

#define CP_ASYNC16(dst, src) \
    asm volatile("cp.async.ca.shared.global [%0], [%1], 16;" :: "r"(dst), "l"(src) : "memory")
#define CP_COMMIT() asm volatile("cp.async.commit_group;" ::: "memory")
#define CP_WAIT1()  asm volatile("cp.async.wait_group 1;" ::: "memory")
#define CP_WAIT0()  asm volatile("cp.async.wait_group 0;" ::: "memory")

// ---------------- elementwise / graph kernels (both graphs batched) ----------

__global__ void k_init(const int* __restrict__ x0, const int* __restrict__ x1,
                       const float* __restrict__ xemb1,
                       const float* __restrict__ xemb2,
                       const float* __restrict__ e1_sl,
                       const float* __restrict__ e2_sl) {
    int idx = blockIdx.x * blockDim.x + threadIdx.x;
    if (idx < 2 * NG * DD) g_gsum[idx] = 0.f;
    if (idx < 2 * NG) g_gcnt[idx] = 0.f;
    if (idx >= 2 * ND) return;
    int gi = idx >= ND;
    int loc = idx - gi * ND;
    int n = loc / DD, d = loc - n * DD;
    const int* xs = gi ? x1 : x0;
    int a = xs[2 * n], c = xs[2 * n + 1];
    float v = xemb1[a * DD + d] + xemb2[c * DD + d];
    g_h[idx] = v;
    g_agg[idx] = v + e1_sl[d] + e2_sl[d];
}

__global__ void k_scatter(const int* __restrict__ ei0, const int* __restrict__ ea0,
                          const int* __restrict__ ei1, const int* __restrict__ ea1,
                          const float* __restrict__ e1l,
                          const float* __restrict__ e2l) {
    int idx = blockIdx.x * blockDim.x + threadIdx.x;
    if (idx >= 2 * ED) return;
    int gi = idx >= ED;
    int loc = idx - gi * ED;
    int e = loc / DD, d = loc - e * DD;
    const int* eis = gi ? ei1 : ei0;
    const int* eas = gi ? ea1 : ea0;
    int src = __ldg(&eis[e]);
    int dst = __ldg(&eis[NE + e]);
    int a0 = __ldg(&eas[2 * e]);
    int a1 = __ldg(&eas[2 * e + 1]);
    size_t base = (size_t)gi * ND;
    float msg = g_h[base + (size_t)src * DD + d] + e1l[a0 * DD + d] + e2l[a1 * DD + d];
    atomicAdd(&g_agg[base + (size_t)dst * DD + d], msg);
}

// split g_agg (both graphs) -> g_Ahi/g_Alo; block 0 zeroes BN stats
__global__ void k_split_agg() {
    int idx = blockIdx.x * blockDim.x + threadIdx.x;
    if (blockIdx.x == 0) {
        for (int t = threadIdx.x; t < 2 * DD; t += blockDim.x) {
            g_sum[t] = 0.f; g_sumsq[t] = 0.f;
        }
    }
    if (idx >= M2PAD * (K1P / 2)) return;
    int m = idx / (K1P / 2);
    int k = (idx - m * (K1P / 2)) * 2;
    int gi = m >= MPAD;
    int node = m - gi * MPAD;
    float v0 = 0.f, v1 = 0.f;
    if (node < NN && k < DD) {
        const float* p = g_agg + (size_t)gi * ND + (size_t)node * DD + k;
        v0 = p[0]; v1 = p[1];
    }
    __nv_bfloat16 h0 = __float2bfloat16(v0);
    __nv_bfloat16 h1 = __float2bfloat16(v1);
    __nv_bfloat16 l0 = __float2bfloat16(v0 - __bfloat162float(h0));
    __nv_bfloat16 l1 = __float2bfloat16(v1 - __bfloat162float(h1));
    size_t o = (size_t)m * K1P + k;
    __nv_bfloat162 th; th.x = h0; th.y = h1;
    __nv_bfloat162 tl; tl.x = l0; tl.y = l1;
    *(__nv_bfloat162*)&g_Ahi[o] = th;
    *(__nv_bfloat162*)&g_Alo[o] = tl;
}

// single kernel: split all W1 and W2 layers
#define W1TOT (NL * N1P * K1P)     // 1,024,000
#define W2TOT (NL * N2P * K2P)     //   972,800
__global__ void k_split_w(const float* __restrict__ W1, const float* __restrict__ W2) {
    int idx = blockIdx.x * blockDim.x + threadIdx.x;
    if (idx < W1TOT) {
        int l = idx / (N1P * K1P);
        int rem = idx - l * (N1P * K1P);
        int n = rem / K1P, k = rem - n * K1P;
        const float* src = W1 + (size_t)l * DD * DD2;
        float v = (n < DD2 && k < DD) ? src[(size_t)k * DD2 + n] : 0.f;
        __nv_bfloat16 h = __float2bfloat16(v);
        g_W1hi[idx] = h;
        g_W1lo[idx] = __float2bfloat16(v - __bfloat162float(h));
    } else if (idx < W1TOT + W2TOT) {
        int j = idx - W1TOT;
        int l = j / (N2P * K2P);
        int rem = j - l * (N2P * K2P);
        int n = rem / K2P, k = rem - n * K2P;
        const float* src = W2 + (size_t)l * DD2 * DD;
        float v = (n < DD && k < DD2) ? src[(size_t)k * DD + n] : 0.f;
        __nv_bfloat16 h = __float2bfloat16(v);
        g_W2hi[j] = h;
        g_W2lo[j] = __float2bfloat16(v - __bfloat162float(h));
    }
}

// ---------------- mma.sync bf16-split GEMM ----------------------------------
// MODE 0: relu(A @ W1 + b1) -> split bf16 -> g_Thi/g_Tlo (stride K2P, n<K2P)
// MODE 1: T @ W2 + b2 -> fp32 g_h2 (+ fused per-graph BN column stats)
// TN in {128, 64}; 8 warps (2 x 4), warp tile 64 x (TN/4).
template <int TN, int MODE>
__global__ void __launch_bounds__(256)
k_mgemm(int l, const float* __restrict__ bias, int colbase) {
    constexpr int KPAD = MODE ? K2P : K1P;
    constexpr int NC   = MODE ? DD  : DD2;
    constexpr int NCHUNK = KPAD / 32;            // 19 or 10
    constexpr int JT = TN / 32;                  // j-tiles per warp (4 or 2)
    constexpr int BMATB = TN * RS;               // bytes per B matrix tile
    constexpr int STAGEB = 2 * MATB + 2 * BMATB; // A(hi,lo) + B(hi,lo)
    const __nv_bfloat16* __restrict__ Ahi = MODE ? g_Thi : g_Ahi;
    const __nv_bfloat16* __restrict__ Alo = MODE ? g_Tlo : g_Alo;
    const __nv_bfloat16* __restrict__ Bhi =
        MODE ? (g_W2hi + (size_t)l * N2P * K2P) : (g_W1hi + (size_t)l * N1P * K1P);
    const __nv_bfloat16* __restrict__ Blo =
        MODE ? (g_W2lo + (size_t)l * N2P * K2P) : (g_W1lo + (size_t)l * N1P * K1P);

    extern __shared__ __align__(16) char smem[];
    const uint32_t sbase = smem_to_u32(smem);
    const int tid = threadIdx.x;
    const int wid = tid >> 5;
    const int lane = tid & 31;
    const int row0 = blockIdx.y * 128;
    const int col0 = colbase + blockIdx.x * TN;
    const int wm = wid & 1;
    const int wn = wid >> 1;
    const int lr = lane & 15;
    const int lc = lane >> 4;

    auto issue = [&](int c) {
        const int buf = c & 1;
        const int k0 = c * 32;
        #pragma unroll
        for (int i = 0; i < 4; i++) {              // A: Ahi/Alo, 128 rows each
            int u = tid + i * 256;                 // 0..1023
            int mat = u >> 9;
            int r = (u >> 2) & 127;
            int c16 = u & 3;
            const __nv_bfloat16* gp = (mat ? Alo : Ahi)
                + (size_t)(row0 + r) * KPAD + k0 + c16 * 8;
            uint32_t dst = sbase + buf * STAGEB + mat * MATB + r * RS + c16 * 16;
            CP_ASYNC16(dst, gp);
        }
        #pragma unroll
        for (int i = 0; i < TN / 32; i++) {        // B: Bhi/Blo, TN rows each
            int u = tid + i * 256;                 // 0..8*TN-1
            int mat = u / (4 * TN);
            int w = u - mat * (4 * TN);
            int r = w >> 2;
            int c16 = w & 3;
            const __nv_bfloat16* gp = (mat ? Blo : Bhi)
                + (size_t)(col0 + r) * KPAD + k0 + c16 * 8;
            uint32_t dst = sbase + buf * STAGEB + 2 * MATB + mat * BMATB
                         + r * RS + c16 * 16;
            CP_ASYNC16(dst, gp);
        }
        CP_COMMIT();
    };

    float acc[4][JT][4] = {};

    issue(0);
    for (int c = 0; c < NCHUNK; c++) {
        if (c + 1 < NCHUNK) { issue(c + 1); CP_WAIT1(); }
        else                { CP_WAIT0(); }
        __syncthreads();
        const uint32_t sb = sbase + (c & 1) * STAGEB;
        #pragma unroll
        for (int s = 0; s < 2; s++) {
            uint32_t ahi[4][4], alo[4][4], bhi[JT][2], blo[JT][2];
            #pragma unroll
            for (int i = 0; i < 4; i++) {
                uint32_t ra = sb + (wm * 64 + i * 16 + lr) * RS + s * 32 + lc * 16;
                LDMX4(ahi[i], ra);
                LDMX4(alo[i], ra + MATB);
            }
            #pragma unroll
            for (int jp = 0; jp < JT / 2; jp++) {
                uint32_t rb = sb + 2 * MATB + (wn * (TN / 4) + jp * 16 + lr) * RS
                            + s * 32 + lc * 16;
                uint32_t t[4];
                LDMX4(t, rb);
                bhi[2 * jp][0] = t[0]; bhi[2 * jp + 1][0] = t[1];
                bhi[2 * jp][1] = t[2]; bhi[2 * jp + 1][1] = t[3];
                LDMX4(t, rb + BMATB);
                blo[2 * jp][0] = t[0]; blo[2 * jp + 1][0] = t[1];
                blo[2 * jp][1] = t[2]; blo[2 * jp + 1][1] = t[3];
            }
            #pragma unroll
            for (int i = 0; i < 4; i++)
                #pragma unroll
                for (int j = 0; j < JT; j++) {
                    MMA_BF16(acc[i][j], ahi[i], bhi[j]);
                    MMA_BF16(acc[i][j], ahi[i], blo[j]);
                    MMA_BF16(acc[i][j], alo[i], bhi[j]);
                }
        }
        __syncthreads();
    }

    if (MODE == 0) {
        #pragma unroll
        for (int i = 0; i < 4; i++) {
            #pragma unroll
            for (int j = 0; j < JT; j++) {
                #pragma unroll
                for (int h = 0; h < 2; h++) {
                    int m = row0 + wm * 64 + i * 16 + (lane >> 2) + h * 8;
                    int n = col0 + wn * (TN / 4) + j * 8 + (lane & 3) * 2;
                    if (n >= K2P) continue;            // T is K2P wide
                    float v0 = acc[i][j][h * 2];
                    float v1 = acc[i][j][h * 2 + 1];
                    if (n < NC) {
                        v0 = fmaxf(v0 + bias[n], 0.f);
                        v1 = fmaxf(v1 + bias[n + 1], 0.f);
                    } else { v0 = 0.f; v1 = 0.f; }
                    __nv_bfloat16 h0 = __float2bfloat16(v0);
                    __nv_bfloat16 h1 = __float2bfloat16(v1);
                    __nv_bfloat16 l0 = __float2bfloat16(v0 - __bfloat162float(h0));
                    __nv_bfloat16 l1 = __float2bfloat16(v1 - __bfloat162float(h1));
                    size_t o = (size_t)m * K2P + n;
                    __nv_bfloat162 th; th.x = h0; th.y = h1;
                    __nv_bfloat162 tl; tl.x = l0; tl.y = l1;
                    *(__nv_bfloat162*)&g_Thi[o] = th;
                    *(__nv_bfloat162*)&g_Tlo[o] = tl;
                }
            }
        }
    } else {
        const int gi = row0 >= MPAD;
        float cs[2 * JT], cq[2 * JT];
        #pragma unroll
        for (int k = 0; k < 2 * JT; k++) { cs[k] = 0.f; cq[k] = 0.f; }
        #pragma unroll
        for (int i = 0; i < 4; i++) {
            #pragma unroll
            for (int j = 0; j < JT; j++) {
                #pragma unroll
                for (int h = 0; h < 2; h++) {
                    int m = row0 + wm * 64 + i * 16 + (lane >> 2) + h * 8;
                    int node = m - gi * MPAD;
                    int n = col0 + wn * (TN / 4) + j * 8 + (lane & 3) * 2;
                    if (node < NN && n < NC) {
                        float v0 = acc[i][j][h * 2]     + bias[n];
                        float v1 = acc[i][j][h * 2 + 1] + bias[n + 1];
                        float2 v; v.x = v0; v.y = v1;
                        *(float2*)&g_h2[((size_t)gi * NN + node) * DD + n] = v;
                        cs[j * 2]     += v0; cq[j * 2]     += v0 * v0;
                        cs[j * 2 + 1] += v1; cq[j * 2 + 1] += v1 * v1;
                    }
                }
            }
        }
        #pragma unroll
        for (int off = 4; off < 32; off <<= 1) {
            #pragma unroll
            for (int k = 0; k < 2 * JT; k++) {
                cs[k] += __shfl_xor_sync(0xffffffffu, cs[k], off);
                cq[k] += __shfl_xor_sync(0xffffffffu, cq[k], off);
            }
        }
        if ((lane >> 2) == 0) {
            #pragma unroll
            for (int k = 0; k < 2 * JT; k++) {
                int n = col0 + wn * (TN / 4) + (k >> 1) * 8 + (lane & 3) * 2 + (k & 1);
                if (n < NC) {
                    atomicAdd(&g_sum[gi * DD + n], cs[k]);
                    atomicAdd(&g_sumsq[gi * DD + n], cq[k]);
                }
            }
        }
    }
}

#define SMEM_128 (2 * (2 * MATB + 2 * 128 * RS))   // 81920
#define SMEM_64  (2 * (2 * MATB + 2 * 64 * RS))    // 61440

// ---------------- BN / pool / pred ------------------------------------------

__global__ void k_bn(const float* __restrict__ gamma_l,
                     const float* __restrict__ beta_l,
                     const float* __restrict__ e1_sl,
                     const float* __restrict__ e2_sl,
                     float* __restrict__ nrep0,
                     float* __restrict__ nrep1, int mode) {
    int idx = blockIdx.x * blockDim.x + threadIdx.x;
    if (idx >= 2 * ND) return;
    int gi = idx >= ND;
    int loc = idx - gi * ND;
    int d = loc % DD;
    float s = g_sum[gi * DD + d];
    float q = g_sumsq[gi * DD + d];
    float mu = s * (1.0f / NN);
    float var = q * (1.0f / NN) - mu * mu;
    float rstd = rsqrtf(var + 1e-5f);
    float v = (g_h2[idx] - mu) * rstd * gamma_l[d] + beta_l[d];
    if (mode == 0) {
        float r = fmaxf(v, 0.f);
        g_h[idx] = r;
        g_agg[idx] = r + e1_sl[d] + e2_sl[d];
    } else {
        (gi ? nrep1 : nrep0)[loc] = v;
    }
}

__global__ void k_pool(const int* __restrict__ batch0,
                       const int* __restrict__ batch1,
                       const float* __restrict__ nrep0,
                       const float* __restrict__ nrep1) {
    int idx = blockIdx.x * blockDim.x + threadIdx.x;
    if (idx >= 2 * ND) return;
    int gi = idx >= ND;
    int loc = idx - gi * ND;
    int n = loc / DD, d = loc - n * DD;
    int b = (gi ? batch1 : batch0)[n];
    float v = (gi ? nrep1 : nrep0)[loc];
    atomicAdd(&g_gsum[((size_t)gi * NG + b) * DD + d], v);
    if (d == 0) atomicAdd(&g_gcnt[gi * NG + b], 1.0f);
}

__global__ void k_pred(const float* __restrict__ predW,
                       const float* __restrict__ predb,
                       float* __restrict__ grep0, float* __restrict__ pred0,
                       float* __restrict__ grep1, float* __restrict__ pred1) {
    int g = blockIdx.x;
    int gi = g >= NG;
    int gl = g - gi * NG;
    float* grep = gi ? grep1 : grep0;
    float* pred = gi ? pred1 : pred0;
    __shared__ float rep[DD];
    float inv = 1.0f / fmaxf(g_gcnt[g], 1.0f);
    for (int d = threadIdx.x; d < DD; d += blockDim.x) {
        float v = g_gsum[(size_t)g * DD + d] * inv;
        rep[d] = v;
        grep[gl * DD + d] = v;
    }
    __syncthreads();
    if (threadIdx.x < NT) {
        int t = threadIdx.x;
        float acc = predb[t];
        for (int d = 0; d < DD; ++d) acc += rep[d] * predW[d * NT + t];
        pred[gl * NT + t] = acc;
    }
}

// ---------------- host orchestration ---------------------------------------

extern "C" void kernel_launch(void* const* d_in, const int* in_sizes, int n_in,
                              void* d_out, int out_size) {
    const int*   x      = (const int*)d_in[0];
    const int*   ei     = (const int*)d_in[1];
    const int*   ea     = (const int*)d_in[2];
    const int*   batch  = (const int*)d_in[3];
    const int*   x1     = (const int*)d_in[4];
    const int*   ei1    = (const int*)d_in[5];
    const int*   ea1    = (const int*)d_in[6];
    const int*   batch1 = (const int*)d_in[7];
    const float* xemb1  = (const float*)d_in[8];
    const float* xemb2  = (const float*)d_in[9];
    const float* eemb1  = (const float*)d_in[10];
    const float* eemb2  = (const float*)d_in[11];
    const float* W1     = (const float*)d_in[12];
    const float* b1     = (const float*)d_in[13];
    const float* W2     = (const float*)d_in[14];
    const float* b2     = (const float*)d_in[15];
    const float* gamma  = (const float*)d_in[16];
    const float* beta   = (const float*)d_in[17];
    const float* predW  = (const float*)d_in[18];
    const float* predb  = (const float*)d_in[19];

    cudaFuncSetAttribute((const void*)k_mgemm<128, 0>,
                         cudaFuncAttributeMaxDynamicSharedMemorySize, SMEM_128);
    cudaFuncSetAttribute((const void*)k_mgemm<128, 1>,
                         cudaFuncAttributeMaxDynamicSharedMemorySize, SMEM_128);
    cudaFuncSetAttribute((const void*)k_mgemm<64, 1>,
                         cudaFuncAttributeMaxDynamicSharedMemorySize, SMEM_64);

    float* out = (float*)d_out;
    float* pred0 = out;
    float* grep0 = out + NG * NT;
    float* nrep0 = out + NG * NT + NG * DD;
    float* pred1 = out + NG * NT + NG * DD + (size_t)NN * DD;
    float* grep1 = pred1 + NG * NT;
    float* nrep1 = pred1 + NG * NT + NG * DD;

    const int BLK = 256;
    const int GRID_2ND = (2 * ND + BLK - 1) / BLK;
    const int GRID_2ED = (2 * ED + BLK - 1) / BLK;
    const int GRID_M2 = M2PAD / 128;  // 782
    const int GRID_SPLIT = (M2PAD * (K1P / 2) + BLK - 1) / BLK;

    k_split_w<<<(W1TOT + W2TOT + 255) / 256, 256>>>(W1, W2);
    k_init<<<GRID_2ND, BLK>>>(x, x1, xemb1, xemb2, eemb1 + 4 * DD, eemb2);

    for (int l = 0; l < NL; ++l) {
        const float* e1l = eemb1 + (size_t)l * NUM_BOND * DD;
        const float* e2l = eemb2 + (size_t)l * NUM_DIR * DD;

        k_scatter<<<GRID_2ED, BLK>>>(ei, ea, ei1, ea1, e1l, e2l);
        k_split_agg<<<GRID_SPLIT, BLK>>>();

        k_mgemm<128, 0><<<dim3(N1P / 128, GRID_M2), 256, SMEM_128>>>(
            l, b1 + (size_t)l * DD2, 0);
        k_mgemm<128, 1><<<dim3(2, GRID_M2), 256, SMEM_128>>>(
            l, b2 + (size_t)l * DD, 0);
        k_mgemm<64, 1><<<dim3(1, GRID_M2), 256, SMEM_64>>>(
            l, b2 + (size_t)l * DD, 256);

        int last = (l == NL - 1);
        const float* e1n = eemb1 + (size_t)(last ? l : l + 1) * NUM_BOND * DD;
        const float* e2n = eemb2 + (size_t)(last ? l : l + 1) * NUM_DIR * DD;
        k_bn<<<GRID_2ND, BLK>>>(gamma + (size_t)l * DD, beta + (size_t)l * DD,
                                e1n + 4 * DD, e2n, nrep0, nrep1, last);
    }

    k_pool<<<GRID_2ND, BLK>>>(batch, batch1, nrep0, nrep1);
    k_pred<<<2 * NG, 128>>>(predW, predb, grep0, pred0, grep1, pred1);
}

// round 10
// speedup vs baseline: 1.4989x; 1.1897x over previous
#include <cuda_runtime.h>
#include <cuda_bf16.h>
#include <cstdint>

// Problem constants
#define NN   50000
#define NE   100000
#define NG   2000
#define DD   300
#define DD2  600
#define NL   5
#define NT   10
#define NUM_BOND 6
#define NUM_DIR  3
#define ND   (NN*DD)
#define ED   (NE*DD)

// Padded GEMM dims (per graph), both graphs stacked along M
#define MPAD  50048          // 391 * 128
#define M2PAD (2*MPAD)       // 100096
#define K1P  320             // GEMM1 K (300 padded)
#define K2P  608             // GEMM2 K / T row stride (600 padded)
#define N1P  640             // GEMM1 N sweep
#define N2P  320             // GEMM2 N (300 padded): 128+128+64

// smem geometry
#define RS     80
#define MATB   (128*RS)

// ---------------- scratch ---------------------------------------------------
__device__ float g_h[2*ND];
__device__ float g_h2[2*ND];
__device__ __nv_bfloat16 g_Ahi[(size_t)M2PAD * K1P];
__device__ __nv_bfloat16 g_Alo[(size_t)M2PAD * K1P];
__device__ __nv_bfloat16 g_Thi[(size_t)M2PAD * K2P];
__device__ __nv_bfloat16 g_Tlo[(size_t)M2PAD * K2P];
__device__ __nv_bfloat16 g_W1hi[NL * N1P * K1P];
__device__ __nv_bfloat16 g_W1lo[NL * N1P * K1P];
__device__ __nv_bfloat16 g_W2hi[NL * N2P * K2P];
__device__ __nv_bfloat16 g_W2lo[NL * N2P * K2P];
__device__ float g_sum[2*DD], g_sumsq[2*DD];
__device__ float g_gsum[2*NG*DD], g_gcnt[2*NG];
// CSR (built once per call; layer-invariant)
__device__ int g_deg[2*NN];
__device__ int g_off[2*(NN+1)];
__device__ int g_cur[2*NN];
__device__ int g_elist[2*NE];     // src | (combo<<17), combo = a0*3+a1

// ---------------- PTX helpers (baseline ISA only) ----------------------------
__device__ __forceinline__ uint32_t smem_to_u32(const void* p) {
    uint32_t a;
    asm("{ .reg .u64 t; cvta.to.shared.u64 t, %1; cvt.u32.u64 %0, t; }" : "=r"(a) : "l"(p));
    return a;
}

#define LDMX4(r, addr) \
    asm volatile("ldmatrix.sync.aligned.m8n8.x4.shared.b16 {%0,%1,%2,%3}, [%4];" \
        : "=r"((r)[0]), "=r"((r)[1]), "=r"((r)[2]), "=r"((r)[3]) : "r"(addr))

#define MMA_BF16(d, a, b) \
    asm volatile("mma.sync.aligned.m16n8k16.row.col.f32.bf16.bf16.f32 " \
        "{%0,%1,%2,%3}, {%4,%5,%6,%7}, {%8,%9}, {%0,%1,%2,%3};" \
        : "+f"((d)[0]), "+f"((d)[1]), "+f"((d)[2]), "+f"((d)[3]) \
        : "r"((a)[0]), "r"((a)[1]), "r"((a)[2]), "r"((a)[3]), \
          "r"((b)[0]), "r"((b)[1]))

#define CP_ASYNC16(dst, src) \
    asm volatile("cp.async.ca.shared.global [%0], [%1], 16;" :: "r"(dst), "l"(src) : "memory")
#define CP_COMMIT() asm volatile("cp.async.commit_group;" ::: "memory")
#define CP_WAIT1()  asm volatile("cp.async.wait_group 1;" ::: "memory")
#define CP_WAIT0()  asm volatile("cp.async.wait_group 0;" ::: "memory")

// ---------------- one-time build kernels -------------------------------------

#define W1TOT (NL * N1P * K1P)
#define W2TOT (NL * N2P * K2P)
// split all weights; also zero CSR degree counters
__global__ void k_split_w(const float* __restrict__ W1, const float* __restrict__ W2) {
    int idx = blockIdx.x * blockDim.x + threadIdx.x;
    if (idx < 2 * NN) g_deg[idx] = 0;
    if (idx < W1TOT) {
        int l = idx / (N1P * K1P);
        int rem = idx - l * (N1P * K1P);
        int n = rem / K1P, k = rem - n * K1P;
        const float* src = W1 + (size_t)l * DD * DD2;
        float v = (n < DD2 && k < DD) ? src[(size_t)k * DD2 + n] : 0.f;
        __nv_bfloat16 h = __float2bfloat16(v);
        g_W1hi[idx] = h;
        g_W1lo[idx] = __float2bfloat16(v - __bfloat162float(h));
    } else if (idx < W1TOT + W2TOT) {
        int j = idx - W1TOT;
        int l = j / (N2P * K2P);
        int rem = j - l * (N2P * K2P);
        int n = rem / K2P, k = rem - n * K2P;
        const float* src = W2 + (size_t)l * DD2 * DD;
        float v = (n < DD && k < DD2) ? src[(size_t)k * DD + n] : 0.f;
        __nv_bfloat16 h = __float2bfloat16(v);
        g_W2hi[j] = h;
        g_W2lo[j] = __float2bfloat16(v - __bfloat162float(h));
    }
}

__global__ void k_count(const int* __restrict__ ei0, const int* __restrict__ ei1) {
    int idx = blockIdx.x * blockDim.x + threadIdx.x;
    if (idx >= 2 * NE) return;
    int gi = idx >= NE;
    int e = idx - gi * NE;
    const int* ei = gi ? ei1 : ei0;
    atomicAdd(&g_deg[gi * NN + ei[NE + e]], 1);
}

// one block per graph: exclusive scan of degrees -> offsets + cursor
__global__ void __launch_bounds__(1024) k_scan() {
    int gi = blockIdx.x;
    const int* deg = g_deg + gi * NN;
    int* off = g_off + gi * (NN + 1);
    int* cur = g_cur + gi * NN;
    __shared__ int partial[1024];
    const int CH = (NN + 1023) / 1024;   // 49
    int t = threadIdx.x;
    int base = t * CH;
    int s = 0;
    for (int i = 0; i < CH; i++) {
        int u = base + i;
        if (u < NN) s += deg[u];
    }
    partial[t] = s;
    __syncthreads();
    if (t == 0) {
        int acc = 0;
        for (int i = 0; i < 1024; i++) { int tmp = partial[i]; partial[i] = acc; acc += tmp; }
    }
    __syncthreads();
    int run = partial[t];
    for (int i = 0; i < CH; i++) {
        int u = base + i;
        if (u < NN) { off[u] = run; cur[u] = run; run += deg[u]; }
    }
    if (t == 0) off[NN] = NE;
}

__global__ void k_fill(const int* __restrict__ ei0, const int* __restrict__ ea0,
                       const int* __restrict__ ei1, const int* __restrict__ ea1) {
    int idx = blockIdx.x * blockDim.x + threadIdx.x;
    if (idx >= 2 * NE) return;
    int gi = idx >= NE;
    int e = idx - gi * NE;
    const int* ei = gi ? ei1 : ei0;
    const int* ea = gi ? ea1 : ea0;
    int src = ei[e];
    int dst = ei[NE + e];
    int a0 = ea[2 * e], a1 = ea[2 * e + 1];
    int pos = atomicAdd(&g_cur[gi * NN + dst], 1);
    g_elist[gi * NE + pos] = src | ((a0 * 3 + a1) << 17);
}

// zero pad regions of Ahi/Alo once per call (cols 300..319 all rows; pad rows)
#define ZR1 (M2PAD*20)
#define ZR2 (2*48*320)           // per array: 2 graphs x 48 pad rows x 320
__global__ void k_zero_pad() {
    int idx = blockIdx.x * blockDim.x + threadIdx.x;
    __nv_bfloat16 z = __float2bfloat16(0.f);
    if (idx < 2 * ZR1) {
        __nv_bfloat16* arr = idx < ZR1 ? g_Ahi : g_Alo;
        int j = idx < ZR1 ? idx : idx - ZR1;
        int r = j / 20, c = 300 + j % 20;
        arr[(size_t)r * K1P + c] = z;
    } else {
        int j = idx - 2 * ZR1;
        if (j >= 2 * ZR2) return;
        __nv_bfloat16* arr = j < ZR2 ? g_Ahi : g_Alo;
        if (j >= ZR2) j -= ZR2;
        int gi = j >= (48 * 320);
        if (gi) j -= 48 * 320;
        int r = gi * MPAD + NN + j / 320;
        int c = j % 320;
        arr[(size_t)r * K1P + c] = z;
    }
}

// ---------------- per-layer kernels ------------------------------------------

// h init (layer input); zeroes pool accumulators
__global__ void k_init(const int* __restrict__ x0, const int* __restrict__ x1,
                       const float* __restrict__ xemb1,
                       const float* __restrict__ xemb2) {
    int idx = blockIdx.x * blockDim.x + threadIdx.x;
    if (idx < 2 * NG * DD) g_gsum[idx] = 0.f;
    if (idx < 2 * NG) g_gcnt[idx] = 0.f;
    if (idx >= 2 * ND) return;
    int gi = idx >= ND;
    int loc = idx - gi * ND;
    int n = loc / DD, d = loc - n * DD;
    const int* xs = gi ? x1 : x0;
    int a = xs[2 * n], c = xs[2 * n + 1];
    g_h[idx] = xemb1[a * DD + d] + xemb2[c * DD + d];
}

// CSR aggregate: agg = h[n] + sl_emb + sum_in(h[src]+eemb), split to bf16 hi/lo.
// Block 0 also zeroes BN stats for this layer.
__global__ void k_aggregate(const float* __restrict__ e1l,
                            const float* __restrict__ e2l) {
    int idx = blockIdx.x * blockDim.x + threadIdx.x;
    if (blockIdx.x == 0) {
        for (int t = threadIdx.x; t < 2 * DD; t += blockDim.x) {
            g_sum[t] = 0.f; g_sumsq[t] = 0.f;
        }
    }
    const int TPG = NN * 75;             // float4 groups per graph
    if (idx >= 2 * TPG) return;
    int gi = idx >= TPG;
    int rem = idx - gi * TPG;
    int n = rem / 75, dq = rem - n * 75;
    int d = dq * 4;
    const float* h = g_h + (size_t)gi * ND;

    float4 v = *(const float4*)&h[(size_t)n * DD + d];
    float4 s1 = *(const float4*)&e1l[4 * DD + d];
    float4 s2 = *(const float4*)&e2l[d];
    v.x += s1.x + s2.x; v.y += s1.y + s2.y;
    v.z += s1.z + s2.z; v.w += s1.w + s2.w;

    int beg = g_off[gi * (NN + 1) + n];
    int end = g_off[gi * (NN + 1) + n + 1];
    const int* el = g_elist + gi * NE;
    for (int j = beg; j < end; j++) {
        int p = el[j];
        int src = p & 0x1FFFF;
        int c = p >> 17;
        int a0 = c / 3, a1 = c - a0 * 3;
        float4 hv = *(const float4*)&h[(size_t)src * DD + d];
        float4 t1 = *(const float4*)&e1l[a0 * DD + d];
        float4 t2 = *(const float4*)&e2l[a1 * DD + d];
        v.x += hv.x + t1.x + t2.x;
        v.y += hv.y + t1.y + t2.y;
        v.z += hv.z + t1.z + t2.z;
        v.w += hv.w + t1.w + t2.w;
    }

    // split to bf16 hi/lo, 8B stores
    union { __nv_bfloat162 b2[2]; uint2 u; } uh, ul;
    __nv_bfloat16 h0 = __float2bfloat16(v.x), h1 = __float2bfloat16(v.y);
    __nv_bfloat16 h2 = __float2bfloat16(v.z), h3 = __float2bfloat16(v.w);
    uh.b2[0].x = h0; uh.b2[0].y = h1; uh.b2[1].x = h2; uh.b2[1].y = h3;
    ul.b2[0].x = __float2bfloat16(v.x - __bfloat162float(h0));
    ul.b2[0].y = __float2bfloat16(v.y - __bfloat162float(h1));
    ul.b2[1].x = __float2bfloat16(v.z - __bfloat162float(h2));
    ul.b2[1].y = __float2bfloat16(v.w - __bfloat162float(h3));
    size_t m = (size_t)(gi * MPAD + n);
    *(uint2*)&g_Ahi[m * K1P + d] = uh.u;
    *(uint2*)&g_Alo[m * K1P + d] = ul.u;
}

// ---------------- mma.sync bf16-split GEMM (unchanged mainloop) --------------
template <int TN, int MODE>
__global__ void __launch_bounds__(256)
k_mgemm(int l, const float* __restrict__ bias, int colbase) {
    constexpr int KPAD = MODE ? K2P : K1P;
    constexpr int NC   = MODE ? DD  : DD2;
    constexpr int NCHUNK = KPAD / 32;
    constexpr int JT = TN / 32;
    constexpr int BMATB = TN * RS;
    constexpr int STAGEB = 2 * MATB + 2 * BMATB;
    const __nv_bfloat16* __restrict__ Ahi = MODE ? g_Thi : g_Ahi;
    const __nv_bfloat16* __restrict__ Alo = MODE ? g_Tlo : g_Alo;
    const __nv_bfloat16* __restrict__ Bhi =
        MODE ? (g_W2hi + (size_t)l * N2P * K2P) : (g_W1hi + (size_t)l * N1P * K1P);
    const __nv_bfloat16* __restrict__ Blo =
        MODE ? (g_W2lo + (size_t)l * N2P * K2P) : (g_W1lo + (size_t)l * N1P * K1P);

    extern __shared__ __align__(16) char smem[];
    const uint32_t sbase = smem_to_u32(smem);
    const int tid = threadIdx.x;
    const int wid = tid >> 5;
    const int lane = tid & 31;
    const int row0 = blockIdx.y * 128;
    const int col0 = colbase + blockIdx.x * TN;
    const int wm = wid & 1;
    const int wn = wid >> 1;
    const int lr = lane & 15;
    const int lc = lane >> 4;

    auto issue = [&](int c) {
        const int buf = c & 1;
        const int k0 = c * 32;
        #pragma unroll
        for (int i = 0; i < 4; i++) {
            int u = tid + i * 256;
            int mat = u >> 9;
            int r = (u >> 2) & 127;
            int c16 = u & 3;
            const __nv_bfloat16* gp = (mat ? Alo : Ahi)
                + (size_t)(row0 + r) * KPAD + k0 + c16 * 8;
            uint32_t dst = sbase + buf * STAGEB + mat * MATB + r * RS + c16 * 16;
            CP_ASYNC16(dst, gp);
        }
        #pragma unroll
        for (int i = 0; i < TN / 32; i++) {
            int u = tid + i * 256;
            int mat = u / (4 * TN);
            int w = u - mat * (4 * TN);
            int r = w >> 2;
            int c16 = w & 3;
            const __nv_bfloat16* gp = (mat ? Blo : Bhi)
                + (size_t)(col0 + r) * KPAD + k0 + c16 * 8;
            uint32_t dst = sbase + buf * STAGEB + 2 * MATB + mat * BMATB
                         + r * RS + c16 * 16;
            CP_ASYNC16(dst, gp);
        }
        CP_COMMIT();
    };

    float acc[4][JT][4] = {};

    issue(0);
    for (int c = 0; c < NCHUNK; c++) {
        if (c + 1 < NCHUNK) { issue(c + 1); CP_WAIT1(); }
        else                { CP_WAIT0(); }
        __syncthreads();
        const uint32_t sb = sbase + (c & 1) * STAGEB;
        #pragma unroll
        for (int s = 0; s < 2; s++) {
            uint32_t ahi[4][4], alo[4][4], bhi[JT][2], blo[JT][2];
            #pragma unroll
            for (int i = 0; i < 4; i++) {
                uint32_t ra = sb + (wm * 64 + i * 16 + lr) * RS + s * 32 + lc * 16;
                LDMX4(ahi[i], ra);
                LDMX4(alo[i], ra + MATB);
            }
            #pragma unroll
            for (int jp = 0; jp < JT / 2; jp++) {
                uint32_t rb = sb + 2 * MATB + (wn * (TN / 4) + jp * 16 + lr) * RS
                            + s * 32 + lc * 16;
                uint32_t t[4];
                LDMX4(t, rb);
                bhi[2 * jp][0] = t[0]; bhi[2 * jp + 1][0] = t[1];
                bhi[2 * jp][1] = t[2]; bhi[2 * jp + 1][1] = t[3];
                LDMX4(t, rb + BMATB);
                blo[2 * jp][0] = t[0]; blo[2 * jp + 1][0] = t[1];
                blo[2 * jp][1] = t[2]; blo[2 * jp + 1][1] = t[3];
            }
            #pragma unroll
            for (int i = 0; i < 4; i++)
                #pragma unroll
                for (int j = 0; j < JT; j++) {
                    MMA_BF16(acc[i][j], ahi[i], bhi[j]);
                    MMA_BF16(acc[i][j], ahi[i], blo[j]);
                    MMA_BF16(acc[i][j], alo[i], bhi[j]);
                }
        }
        __syncthreads();
    }

    if (MODE == 0) {
        #pragma unroll
        for (int i = 0; i < 4; i++) {
            #pragma unroll
            for (int j = 0; j < JT; j++) {
                #pragma unroll
                for (int h = 0; h < 2; h++) {
                    int m = row0 + wm * 64 + i * 16 + (lane >> 2) + h * 8;
                    int n = col0 + wn * (TN / 4) + j * 8 + (lane & 3) * 2;
                    if (n >= K2P) continue;
                    float v0 = acc[i][j][h * 2];
                    float v1 = acc[i][j][h * 2 + 1];
                    if (n < NC) {
                        v0 = fmaxf(v0 + bias[n], 0.f);
                        v1 = fmaxf(v1 + bias[n + 1], 0.f);
                    } else { v0 = 0.f; v1 = 0.f; }
                    __nv_bfloat16 h0 = __float2bfloat16(v0);
                    __nv_bfloat16 h1 = __float2bfloat16(v1);
                    __nv_bfloat16 l0 = __float2bfloat16(v0 - __bfloat162float(h0));
                    __nv_bfloat16 l1 = __float2bfloat16(v1 - __bfloat162float(h1));
                    size_t o = (size_t)m * K2P + n;
                    __nv_bfloat162 th; th.x = h0; th.y = h1;
                    __nv_bfloat162 tl; tl.x = l0; tl.y = l1;
                    *(__nv_bfloat162*)&g_Thi[o] = th;
                    *(__nv_bfloat162*)&g_Tlo[o] = tl;
                }
            }
        }
    } else {
        const int gi = row0 >= MPAD;
        float cs[2 * JT], cq[2 * JT];
        #pragma unroll
        for (int k = 0; k < 2 * JT; k++) { cs[k] = 0.f; cq[k] = 0.f; }
        #pragma unroll
        for (int i = 0; i < 4; i++) {
            #pragma unroll
            for (int j = 0; j < JT; j++) {
                #pragma unroll
                for (int h = 0; h < 2; h++) {
                    int m = row0 + wm * 64 + i * 16 + (lane >> 2) + h * 8;
                    int node = m - gi * MPAD;
                    int n = col0 + wn * (TN / 4) + j * 8 + (lane & 3) * 2;
                    if (node < NN && n < NC) {
                        float v0 = acc[i][j][h * 2]     + bias[n];
                        float v1 = acc[i][j][h * 2 + 1] + bias[n + 1];
                        float2 v; v.x = v0; v.y = v1;
                        *(float2*)&g_h2[((size_t)gi * NN + node) * DD + n] = v;
                        cs[j * 2]     += v0; cq[j * 2]     += v0 * v0;
                        cs[j * 2 + 1] += v1; cq[j * 2 + 1] += v1 * v1;
                    }
                }
            }
        }
        #pragma unroll
        for (int off = 4; off < 32; off <<= 1) {
            #pragma unroll
            for (int k = 0; k < 2 * JT; k++) {
                cs[k] += __shfl_xor_sync(0xffffffffu, cs[k], off);
                cq[k] += __shfl_xor_sync(0xffffffffu, cq[k], off);
            }
        }
        if ((lane >> 2) == 0) {
            #pragma unroll
            for (int k = 0; k < 2 * JT; k++) {
                int n = col0 + wn * (TN / 4) + (k >> 1) * 8 + (lane & 3) * 2 + (k & 1);
                if (n < NC) {
                    atomicAdd(&g_sum[gi * DD + n], cs[k]);
                    atomicAdd(&g_sumsq[gi * DD + n], cq[k]);
                }
            }
        }
    }
}

#define SMEM_128 (2 * (2 * MATB + 2 * 128 * RS))   // 81920
#define SMEM_64  (2 * (2 * MATB + 2 * 64 * RS))    // 61440

// ---------------- BN / pool / pred ------------------------------------------

__global__ void k_bn(const float* __restrict__ gamma_l,
                     const float* __restrict__ beta_l,
                     float* __restrict__ nrep0,
                     float* __restrict__ nrep1, int mode) {
    int idx = blockIdx.x * blockDim.x + threadIdx.x;
    if (idx >= 2 * ND) return;
    int gi = idx >= ND;
    int loc = idx - gi * ND;
    int d = loc % DD;
    float s = g_sum[gi * DD + d];
    float q = g_sumsq[gi * DD + d];
    float mu = s * (1.0f / NN);
    float var = q * (1.0f / NN) - mu * mu;
    float rstd = rsqrtf(var + 1e-5f);
    float v = (g_h2[idx] - mu) * rstd * gamma_l[d] + beta_l[d];
    if (mode == 0) {
        g_h[idx] = fmaxf(v, 0.f);
    } else {
        (gi ? nrep1 : nrep0)[loc] = v;
    }
}

__global__ void k_pool(const int* __restrict__ batch0,
                       const int* __restrict__ batch1,
                       const float* __restrict__ nrep0,
                       const float* __restrict__ nrep1) {
    int idx = blockIdx.x * blockDim.x + threadIdx.x;
    if (idx >= 2 * ND) return;
    int gi = idx >= ND;
    int loc = idx - gi * ND;
    int n = loc / DD, d = loc - n * DD;
    int b = (gi ? batch1 : batch0)[n];
    float v = (gi ? nrep1 : nrep0)[loc];
    atomicAdd(&g_gsum[((size_t)gi * NG + b) * DD + d], v);
    if (d == 0) atomicAdd(&g_gcnt[gi * NG + b], 1.0f);
}

__global__ void k_pred(const float* __restrict__ predW,
                       const float* __restrict__ predb,
                       float* __restrict__ grep0, float* __restrict__ pred0,
                       float* __restrict__ grep1, float* __restrict__ pred1) {
    int g = blockIdx.x;
    int gi = g >= NG;
    int gl = g - gi * NG;
    float* grep = gi ? grep1 : grep0;
    float* pred = gi ? pred1 : pred0;
    __shared__ float rep[DD];
    float inv = 1.0f / fmaxf(g_gcnt[g], 1.0f);
    for (int d = threadIdx.x; d < DD; d += blockDim.x) {
        float v = g_gsum[(size_t)g * DD + d] * inv;
        rep[d] = v;
        grep[gl * DD + d] = v;
    }
    __syncthreads();
    if (threadIdx.x < NT) {
        int t = threadIdx.x;
        float acc = predb[t];
        for (int d = 0; d < DD; ++d) acc += rep[d] * predW[d * NT + t];
        pred[gl * NT + t] = acc;
    }
}

// ---------------- host orchestration ---------------------------------------

extern "C" void kernel_launch(void* const* d_in, const int* in_sizes, int n_in,
                              void* d_out, int out_size) {
    const int*   x      = (const int*)d_in[0];
    const int*   ei     = (const int*)d_in[1];
    const int*   ea     = (const int*)d_in[2];
    const int*   batch  = (const int*)d_in[3];
    const int*   x1     = (const int*)d_in[4];
    const int*   ei1    = (const int*)d_in[5];
    const int*   ea1    = (const int*)d_in[6];
    const int*   batch1 = (const int*)d_in[7];
    const float* xemb1  = (const float*)d_in[8];
    const float* xemb2  = (const float*)d_in[9];
    const float* eemb1  = (const float*)d_in[10];
    const float* eemb2  = (const float*)d_in[11];
    const float* W1     = (const float*)d_in[12];
    const float* b1     = (const float*)d_in[13];
    const float* W2     = (const float*)d_in[14];
    const float* b2     = (const float*)d_in[15];
    const float* gamma  = (const float*)d_in[16];
    const float* beta   = (const float*)d_in[17];
    const float* predW  = (const float*)d_in[18];
    const float* predb  = (const float*)d_in[19];

    cudaFuncSetAttribute((const void*)k_mgemm<128, 0>,
                         cudaFuncAttributeMaxDynamicSharedMemorySize, SMEM_128);
    cudaFuncSetAttribute((const void*)k_mgemm<128, 1>,
                         cudaFuncAttributeMaxDynamicSharedMemorySize, SMEM_128);
    cudaFuncSetAttribute((const void*)k_mgemm<64, 1>,
                         cudaFuncAttributeMaxDynamicSharedMemorySize, SMEM_64);

    float* out = (float*)d_out;
    float* pred0 = out;
    float* grep0 = out + NG * NT;
    float* nrep0 = out + NG * NT + NG * DD;
    float* pred1 = out + NG * NT + NG * DD + (size_t)NN * DD;
    float* grep1 = pred1 + NG * NT;
    float* nrep1 = pred1 + NG * NT + NG * DD;

    const int BLK = 256;
    const int GRID_2ND = (2 * ND + BLK - 1) / BLK;
    const int GRID_2NE = (2 * NE + BLK - 1) / BLK;
    const int GRID_M2 = M2PAD / 128;  // 782
    const int GRID_AGG = (2 * NN * 75 + BLK - 1) / BLK;
    const int GRID_ZP = (2 * ZR1 + 2 * ZR2 + BLK - 1) / BLK;

    // one-time builds
    k_split_w<<<(W1TOT + W2TOT + 255) / 256, 256>>>(W1, W2);   // + zero deg
    k_count<<<GRID_2NE, BLK>>>(ei, ei1);
    k_scan<<<2, 1024>>>();
    k_fill<<<GRID_2NE, BLK>>>(ei, ea, ei1, ea1);
    k_zero_pad<<<GRID_ZP, BLK>>>();
    k_init<<<GRID_2ND, BLK>>>(x, x1, xemb1, xemb2);

    for (int l = 0; l < NL; ++l) {
        const float* e1l = eemb1 + (size_t)l * NUM_BOND * DD;
        const float* e2l = eemb2 + (size_t)l * NUM_DIR * DD;

        k_aggregate<<<GRID_AGG, BLK>>>(e1l, e2l);

        k_mgemm<128, 0><<<dim3(N1P / 128, GRID_M2), 256, SMEM_128>>>(
            l, b1 + (size_t)l * DD2, 0);
        k_mgemm<128, 1><<<dim3(2, GRID_M2), 256, SMEM_128>>>(
            l, b2 + (size_t)l * DD, 0);
        k_mgemm<64, 1><<<dim3(1, GRID_M2), 256, SMEM_64>>>(
            l, b2 + (size_t)l * DD, 256);

        int last = (l == NL - 1);
        k_bn<<<GRID_2ND, BLK>>>(gamma + (size_t)l * DD, beta + (size_t)l * DD,
                                nrep0, nrep1, last);
    }

    k_pool<<<GRID_2ND, BLK>>>(batch, batch1, nrep0, nrep1);
    k_pred<<<2 * NG, 128>>>(predW, predb, grep0, pred0, grep1, pred1);
}

// round 14
// speedup vs baseline: 1.5797x; 1.0539x over previous
#include <cuda_runtime.h>
#include <cuda_bf16.h>
#include <cstdint>

// Problem constants
#define NN   50000
#define NE   100000
#define NG   2000
#define DD   300
#define DD2  600
#define NL   5
#define NT   10
#define NUM_BOND 6
#define NUM_DIR  3
#define ND   (NN*DD)
#define ED   (NE*DD)

// Padded GEMM dims (per graph), both graphs stacked along M
#define MPAD  50048          // 391 * 128
#define M2PAD (2*MPAD)       // 100096
#define K1P  320             // GEMM1 K (300 padded)
#define K2P  608             // GEMM2 K / T row stride (600 padded)
#define N1P  640             // GEMM1 N sweep
#define N2P  320             // GEMM2 N (300 padded): 128+128+64

// smem geometry
#define RS     80
#define MATB   (128*RS)

// ---------------- scratch ---------------------------------------------------
__device__ float g_h[2*ND];      // initial features only (layer 0 input)
__device__ float g_h2[2*ND];     // raw GEMM2 output (pre-BN)
__device__ __nv_bfloat16 g_Ahi[(size_t)M2PAD * K1P];
__device__ __nv_bfloat16 g_Alo[(size_t)M2PAD * K1P];
__device__ __nv_bfloat16 g_Thi[(size_t)M2PAD * K2P];
__device__ __nv_bfloat16 g_Tlo[(size_t)M2PAD * K2P];
__device__ __nv_bfloat16 g_W1hi[NL * N1P * K1P];
__device__ __nv_bfloat16 g_W1lo[NL * N1P * K1P];
__device__ __nv_bfloat16 g_W2hi[NL * N2P * K2P];
__device__ __nv_bfloat16 g_W2lo[NL * N2P * K2P];
__device__ float g_sum[2*2*DD], g_sumsq[2*2*DD];   // double-buffered by layer&1
__device__ float g_gsum[2*NG*DD], g_gcnt[2*NG];
// CSR (built once per call; layer-invariant)
__device__ int g_deg[2*NN];
__device__ int g_off[2*(NN+1)];
__device__ int g_cur[2*NN];
__device__ int g_elist[2*NE];     // src | (combo<<17), combo = a0*3+a1

// ---------------- PTX helpers (baseline ISA only) ----------------------------
__device__ __forceinline__ uint32_t smem_to_u32(const void* p) {
    uint32_t a;
    asm("{ .reg .u64 t; cvta.to.shared.u64 t, %1; cvt.u32.u64 %0, t; }" : "=r"(a) : "l"(p));
    return a;
}

#define LDMX4(r, addr) \
    asm volatile("ldmatrix.sync.aligned.m8n8.x4.shared.b16 {%0,%1,%2,%3}, [%4];" \
        : "=r"((r)[0]), "=r"((r)[1]), "=r"((r)[2]), "=r"((r)[3]) : "r"(addr))

#define MMA_BF16(d, a, b) \
    asm volatile("mma.sync.aligned.m16n8k16.row.col.f32.bf16.bf16.f32 " \
        "{%0,%1,%2,%3}, {%4,%5,%6,%7}, {%8,%9}, {%0,%1,%2,%3};" \
        : "+f"((d)[0]), "+f"((d)[1]), "+f"((d)[2]), "+f"((d)[3]) \
        : "r"((a)[0]), "r"((a)[1]), "r"((a)[2]), "r"((a)[3]), \
          "r"((b)[0]), "r"((b)[1]))

#define CP_ASYNC16(dst, src) \
    asm volatile("cp.async.ca.shared.global [%0], [%1], 16;" :: "r"(dst), "l"(src) : "memory")
#define CP_COMMIT() asm volatile("cp.async.commit_group;" ::: "memory")
#define CP_WAIT1()  asm volatile("cp.async.wait_group 1;" ::: "memory")
#define CP_WAIT0()  asm volatile("cp.async.wait_group 0;" ::: "memory")

// ---------------- one-time build kernels -------------------------------------

#define W1TOT (NL * N1P * K1P)
#define W2TOT (NL * N2P * K2P)
__global__ void k_split_w(const float* __restrict__ W1, const float* __restrict__ W2) {
    int idx = blockIdx.x * blockDim.x + threadIdx.x;
    if (idx < 2 * NN) g_deg[idx] = 0;
    if (idx < W1TOT) {
        int l = idx / (N1P * K1P);
        int rem = idx - l * (N1P * K1P);
        int n = rem / K1P, k = rem - n * K1P;
        const float* src = W1 + (size_t)l * DD * DD2;
        float v = (n < DD2 && k < DD) ? src[(size_t)k * DD2 + n] : 0.f;
        __nv_bfloat16 h = __float2bfloat16(v);
        g_W1hi[idx] = h;
        g_W1lo[idx] = __float2bfloat16(v - __bfloat162float(h));
    } else if (idx < W1TOT + W2TOT) {
        int j = idx - W1TOT;
        int l = j / (N2P * K2P);
        int rem = j - l * (N2P * K2P);
        int n = rem / K2P, k = rem - n * K2P;
        const float* src = W2 + (size_t)l * DD2 * DD;
        float v = (n < DD && k < DD2) ? src[(size_t)k * DD + n] : 0.f;
        __nv_bfloat16 h = __float2bfloat16(v);
        g_W2hi[j] = h;
        g_W2lo[j] = __float2bfloat16(v - __bfloat162float(h));
    }
}

__global__ void k_count(const int* __restrict__ ei0, const int* __restrict__ ei1) {
    int idx = blockIdx.x * blockDim.x + threadIdx.x;
    if (idx >= 2 * NE) return;
    int gi = idx >= NE;
    int e = idx - gi * NE;
    const int* ei = gi ? ei1 : ei0;
    atomicAdd(&g_deg[gi * NN + ei[NE + e]], 1);
}

__global__ void __launch_bounds__(1024) k_scan() {
    int gi = blockIdx.x;
    const int* deg = g_deg + gi * NN;
    int* off = g_off + gi * (NN + 1);
    int* cur = g_cur + gi * NN;
    __shared__ int partial[1024];
    const int CH = (NN + 1023) / 1024;
    int t = threadIdx.x;
    int base = t * CH;
    int s = 0;
    for (int i = 0; i < CH; i++) {
        int u = base + i;
        if (u < NN) s += deg[u];
    }
    partial[t] = s;
    __syncthreads();
    if (t == 0) {
        int acc = 0;
        for (int i = 0; i < 1024; i++) { int tmp = partial[i]; partial[i] = acc; acc += tmp; }
    }
    __syncthreads();
    int run = partial[t];
    for (int i = 0; i < CH; i++) {
        int u = base + i;
        if (u < NN) { off[u] = run; cur[u] = run; run += deg[u]; }
    }
    if (t == 0) off[NN] = NE;
}

__global__ void k_fill(const int* __restrict__ ei0, const int* __restrict__ ea0,
                       const int* __restrict__ ei1, const int* __restrict__ ea1) {
    int idx = blockIdx.x * blockDim.x + threadIdx.x;
    if (idx >= 2 * NE) return;
    int gi = idx >= NE;
    int e = idx - gi * NE;
    const int* ei = gi ? ei1 : ei0;
    const int* ea = gi ? ea1 : ea0;
    int src = ei[e];
    int dst = ei[NE + e];
    int a0 = ea[2 * e], a1 = ea[2 * e + 1];
    int pos = atomicAdd(&g_cur[gi * NN + dst], 1);
    g_elist[gi * NE + pos] = src | ((a0 * 3 + a1) << 17);
}

// zero pad regions of Ahi/Alo once per call
#define ZR1 (M2PAD*20)
#define ZR2 (2*48*320)
__global__ void k_zero_pad() {
    int idx = blockIdx.x * blockDim.x + threadIdx.x;
    __nv_bfloat16 z = __float2bfloat16(0.f);
    if (idx < 2 * ZR1) {
        __nv_bfloat16* arr = idx < ZR1 ? g_Ahi : g_Alo;
        int j = idx < ZR1 ? idx : idx - ZR1;
        int r = j / 20, c = 300 + j % 20;
        arr[(size_t)r * K1P + c] = z;
    } else {
        int j = idx - 2 * ZR1;
        if (j >= 2 * ZR2) return;
        __nv_bfloat16* arr = j < ZR2 ? g_Ahi : g_Alo;
        if (j >= ZR2) j -= ZR2;
        int gi = j >= (48 * 320);
        if (gi) j -= 48 * 320;
        int r = gi * MPAD + NN + j / 320;
        int c = j % 320;
        arr[(size_t)r * K1P + c] = z;
    }
}

// ---------------- per-layer kernels ------------------------------------------

__global__ void k_init(const int* __restrict__ x0, const int* __restrict__ x1,
                       const float* __restrict__ xemb1,
                       const float* __restrict__ xemb2) {
    int idx = blockIdx.x * blockDim.x + threadIdx.x;
    if (idx < 2 * NG * DD) g_gsum[idx] = 0.f;
    if (idx < 2 * NG) g_gcnt[idx] = 0.f;
    if (idx >= 2 * ND) return;
    int gi = idx >= ND;
    int loc = idx - gi * ND;
    int n = loc / DD, d = loc - n * DD;
    const int* xs = gi ? x1 : x0;
    int a = xs[2 * n], c = xs[2 * n + 1];
    g_h[idx] = xemb1[a * DD + d] + xemb2[c * DD + d];
}

// CSR aggregate with fused BN-apply-on-read (layers > 0) and bf16 split store.
// l==0: src = g_h raw. l>0: src = relu(bn_{l-1}(g_h2)) computed on the fly.
// Block 0 zeroes this layer's stats buffer (l&1); BN params read from (l-1)&1.
__global__ void k_aggregate(int l,
                            const float* __restrict__ e1l,
                            const float* __restrict__ e2l,
                            const float* __restrict__ gamma_p,
                            const float* __restrict__ beta_p) {
    int idx = blockIdx.x * blockDim.x + threadIdx.x;
    if (blockIdx.x == 0) {
        int zb = (l & 1) * 2 * DD;
        for (int t = threadIdx.x; t < 2 * DD; t += blockDim.x) {
            g_sum[zb + t] = 0.f; g_sumsq[zb + t] = 0.f;
        }
    }
    const int TPG = NN * 75;
    if (idx >= 2 * TPG) return;
    int gi = idx >= TPG;
    int rem = idx - gi * TPG;
    int n = rem / 75, dq = rem - n * 75;
    int d = dq * 4;
    const float* src = (l == 0) ? (g_h + (size_t)gi * ND) : (g_h2 + (size_t)gi * ND);

    // per-thread BN scale/shift for the 4 d's
    float4 scale, shift;
    if (l == 0) {
        scale = make_float4(1.f, 1.f, 1.f, 1.f);
        shift = make_float4(0.f, 0.f, 0.f, 0.f);
    } else {
        int pb = ((l - 1) & 1) * 2 * DD + gi * DD;
        #pragma unroll
        for (int k = 0; k < 4; k++) {
            float s = g_sum[pb + d + k];
            float q = g_sumsq[pb + d + k];
            float mu = s * (1.0f / NN);
            float var = q * (1.0f / NN) - mu * mu;
            float rstd = rsqrtf(var + 1e-5f);
            float sc = rstd * gamma_p[d + k];
            float sh = beta_p[d + k] - mu * sc;
            (&scale.x)[k] = sc;
            (&shift.x)[k] = sh;
        }
    }

    auto ldsrc = [&](int node) -> float4 {
        float4 r = *(const float4*)&src[(size_t)node * DD + d];
        if (l > 0) {
            r.x = fmaxf(fmaf(r.x, scale.x, shift.x), 0.f);
            r.y = fmaxf(fmaf(r.y, scale.y, shift.y), 0.f);
            r.z = fmaxf(fmaf(r.z, scale.z, shift.z), 0.f);
            r.w = fmaxf(fmaf(r.w, scale.w, shift.w), 0.f);
        }
        return r;
    };

    float4 v = ldsrc(n);
    float4 s1 = *(const float4*)&e1l[4 * DD + d];
    float4 s2 = *(const float4*)&e2l[d];
    v.x += s1.x + s2.x; v.y += s1.y + s2.y;
    v.z += s1.z + s2.z; v.w += s1.w + s2.w;

    int beg = g_off[gi * (NN + 1) + n];
    int end = g_off[gi * (NN + 1) + n + 1];
    const int* el = g_elist + gi * NE;
    for (int j = beg; j < end; j++) {
        int p = el[j];
        int srcn = p & 0x1FFFF;
        int c = p >> 17;
        int a0 = c / 3, a1 = c - a0 * 3;
        float4 hv = ldsrc(srcn);
        float4 t1 = *(const float4*)&e1l[a0 * DD + d];
        float4 t2 = *(const float4*)&e2l[a1 * DD + d];
        v.x += hv.x + t1.x + t2.x;
        v.y += hv.y + t1.y + t2.y;
        v.z += hv.z + t1.z + t2.z;
        v.w += hv.w + t1.w + t2.w;
    }

    union { __nv_bfloat162 b2[2]; uint2 u; } uh, ul;
    __nv_bfloat16 h0 = __float2bfloat16(v.x), h1 = __float2bfloat16(v.y);
    __nv_bfloat16 h2 = __float2bfloat16(v.z), h3 = __float2bfloat16(v.w);
    uh.b2[0].x = h0; uh.b2[0].y = h1; uh.b2[1].x = h2; uh.b2[1].y = h3;
    ul.b2[0].x = __float2bfloat16(v.x - __bfloat162float(h0));
    ul.b2[0].y = __float2bfloat16(v.y - __bfloat162float(h1));
    ul.b2[1].x = __float2bfloat16(v.z - __bfloat162float(h2));
    ul.b2[1].y = __float2bfloat16(v.w - __bfloat162float(h3));
    size_t m = (size_t)(gi * MPAD + n);
    *(uint2*)&g_Ahi[m * K1P + d] = uh.u;
    *(uint2*)&g_Alo[m * K1P + d] = ul.u;
}

// ---------------- mma.sync bf16-split GEMM (unchanged mainloop) --------------
template <int TN, int MODE>
__global__ void __launch_bounds__(256)
k_mgemm(int l, const float* __restrict__ bias, int colbase) {
    constexpr int KPAD = MODE ? K2P : K1P;
    constexpr int NC   = MODE ? DD  : DD2;
    constexpr int NCHUNK = KPAD / 32;
    constexpr int JT = TN / 32;
    constexpr int BMATB = TN * RS;
    constexpr int STAGEB = 2 * MATB + 2 * BMATB;
    const __nv_bfloat16* __restrict__ Ahi = MODE ? g_Thi : g_Ahi;
    const __nv_bfloat16* __restrict__ Alo = MODE ? g_Tlo : g_Alo;
    const __nv_bfloat16* __restrict__ Bhi =
        MODE ? (g_W2hi + (size_t)l * N2P * K2P) : (g_W1hi + (size_t)l * N1P * K1P);
    const __nv_bfloat16* __restrict__ Blo =
        MODE ? (g_W2lo + (size_t)l * N2P * K2P) : (g_W1lo + (size_t)l * N1P * K1P);

    extern __shared__ __align__(16) char smem[];
    const uint32_t sbase = smem_to_u32(smem);
    const int tid = threadIdx.x;
    const int wid = tid >> 5;
    const int lane = tid & 31;
    const int row0 = blockIdx.y * 128;
    const int col0 = colbase + blockIdx.x * TN;
    const int wm = wid & 1;
    const int wn = wid >> 1;
    const int lr = lane & 15;
    const int lc = lane >> 4;

    auto issue = [&](int c) {
        const int buf = c & 1;
        const int k0 = c * 32;
        #pragma unroll
        for (int i = 0; i < 4; i++) {
            int u = tid + i * 256;
            int mat = u >> 9;
            int r = (u >> 2) & 127;
            int c16 = u & 3;
            const __nv_bfloat16* gp = (mat ? Alo : Ahi)
                + (size_t)(row0 + r) * KPAD + k0 + c16 * 8;
            uint32_t dst = sbase + buf * STAGEB + mat * MATB + r * RS + c16 * 16;
            CP_ASYNC16(dst, gp);
        }
        #pragma unroll
        for (int i = 0; i < TN / 32; i++) {
            int u = tid + i * 256;
            int mat = u / (4 * TN);
            int w = u - mat * (4 * TN);
            int r = w >> 2;
            int c16 = w & 3;
            const __nv_bfloat16* gp = (mat ? Blo : Bhi)
                + (size_t)(col0 + r) * KPAD + k0 + c16 * 8;
            uint32_t dst = sbase + buf * STAGEB + 2 * MATB + mat * BMATB
                         + r * RS + c16 * 16;
            CP_ASYNC16(dst, gp);
        }
        CP_COMMIT();
    };

    float acc[4][JT][4] = {};

    issue(0);
    for (int c = 0; c < NCHUNK; c++) {
        if (c + 1 < NCHUNK) { issue(c + 1); CP_WAIT1(); }
        else                { CP_WAIT0(); }
        __syncthreads();
        const uint32_t sb = sbase + (c & 1) * STAGEB;
        #pragma unroll
        for (int s = 0; s < 2; s++) {
            uint32_t ahi[4][4], alo[4][4], bhi[JT][2], blo[JT][2];
            #pragma unroll
            for (int i = 0; i < 4; i++) {
                uint32_t ra = sb + (wm * 64 + i * 16 + lr) * RS + s * 32 + lc * 16;
                LDMX4(ahi[i], ra);
                LDMX4(alo[i], ra + MATB);
            }
            #pragma unroll
            for (int jp = 0; jp < JT / 2; jp++) {
                uint32_t rb = sb + 2 * MATB + (wn * (TN / 4) + jp * 16 + lr) * RS
                            + s * 32 + lc * 16;
                uint32_t t[4];
                LDMX4(t, rb);
                bhi[2 * jp][0] = t[0]; bhi[2 * jp + 1][0] = t[1];
                bhi[2 * jp][1] = t[2]; bhi[2 * jp + 1][1] = t[3];
                LDMX4(t, rb + BMATB);
                blo[2 * jp][0] = t[0]; blo[2 * jp + 1][0] = t[1];
                blo[2 * jp][1] = t[2]; blo[2 * jp + 1][1] = t[3];
            }
            #pragma unroll
            for (int i = 0; i < 4; i++)
                #pragma unroll
                for (int j = 0; j < JT; j++) {
                    MMA_BF16(acc[i][j], ahi[i], bhi[j]);
                    MMA_BF16(acc[i][j], ahi[i], blo[j]);
                    MMA_BF16(acc[i][j], alo[i], bhi[j]);
                }
        }
        __syncthreads();
    }

    if (MODE == 0) {
        #pragma unroll
        for (int i = 0; i < 4; i++) {
            #pragma unroll
            for (int j = 0; j < JT; j++) {
                #pragma unroll
                for (int h = 0; h < 2; h++) {
                    int m = row0 + wm * 64 + i * 16 + (lane >> 2) + h * 8;
                    int n = col0 + wn * (TN / 4) + j * 8 + (lane & 3) * 2;
                    if (n >= K2P) continue;
                    float v0 = acc[i][j][h * 2];
                    float v1 = acc[i][j][h * 2 + 1];
                    if (n < NC) {
                        v0 = fmaxf(v0 + bias[n], 0.f);
                        v1 = fmaxf(v1 + bias[n + 1], 0.f);
                    } else { v0 = 0.f; v1 = 0.f; }
                    __nv_bfloat16 h0 = __float2bfloat16(v0);
                    __nv_bfloat16 h1 = __float2bfloat16(v1);
                    __nv_bfloat16 l0 = __float2bfloat16(v0 - __bfloat162float(h0));
                    __nv_bfloat16 l1 = __float2bfloat16(v1 - __bfloat162float(h1));
                    size_t o = (size_t)m * K2P + n;
                    __nv_bfloat162 th; th.x = h0; th.y = h1;
                    __nv_bfloat162 tl; tl.x = l0; tl.y = l1;
                    *(__nv_bfloat162*)&g_Thi[o] = th;
                    *(__nv_bfloat162*)&g_Tlo[o] = tl;
                }
            }
        }
    } else {
        const int gi = row0 >= MPAD;
        const int sb2 = (l & 1) * 2 * DD + gi * DD;
        float cs[2 * JT], cq[2 * JT];
        #pragma unroll
        for (int k = 0; k < 2 * JT; k++) { cs[k] = 0.f; cq[k] = 0.f; }
        #pragma unroll
        for (int i = 0; i < 4; i++) {
            #pragma unroll
            for (int j = 0; j < JT; j++) {
                #pragma unroll
                for (int h = 0; h < 2; h++) {
                    int m = row0 + wm * 64 + i * 16 + (lane >> 2) + h * 8;
                    int node = m - gi * MPAD;
                    int n = col0 + wn * (TN / 4) + j * 8 + (lane & 3) * 2;
                    if (node < NN && n < NC) {
                        float v0 = acc[i][j][h * 2]     + bias[n];
                        float v1 = acc[i][j][h * 2 + 1] + bias[n + 1];
                        float2 v; v.x = v0; v.y = v1;
                        *(float2*)&g_h2[((size_t)gi * NN + node) * DD + n] = v;
                        cs[j * 2]     += v0; cq[j * 2]     += v0 * v0;
                        cs[j * 2 + 1] += v1; cq[j * 2 + 1] += v1 * v1;
                    }
                }
            }
        }
        #pragma unroll
        for (int off = 4; off < 32; off <<= 1) {
            #pragma unroll
            for (int k = 0; k < 2 * JT; k++) {
                cs[k] += __shfl_xor_sync(0xffffffffu, cs[k], off);
                cq[k] += __shfl_xor_sync(0xffffffffu, cq[k], off);
            }
        }
        if ((lane >> 2) == 0) {
            #pragma unroll
            for (int k = 0; k < 2 * JT; k++) {
                int n = col0 + wn * (TN / 4) + (k >> 1) * 8 + (lane & 3) * 2 + (k & 1);
                if (n < NC) {
                    atomicAdd(&g_sum[sb2 + n], cs[k]);
                    atomicAdd(&g_sumsq[sb2 + n], cq[k]);
                }
            }
        }
    }
}

#define SMEM_128 (2 * (2 * MATB + 2 * 128 * RS))   // 81920
#define SMEM_64  (2 * (2 * MATB + 2 * 64 * RS))    // 61440

// ---------------- final BN + pool (fused) + pred ------------------------------

// last layer: nrep = bn(h2) (no relu); pool atomics fused
__global__ void k_bnpool(const float* __restrict__ gamma_l,
                         const float* __restrict__ beta_l,
                         const int* __restrict__ batch0,
                         const int* __restrict__ batch1,
                         float* __restrict__ nrep0,
                         float* __restrict__ nrep1) {
    int idx = blockIdx.x * blockDim.x + threadIdx.x;
    if (idx >= 2 * ND) return;
    int gi = idx >= ND;
    int loc = idx - gi * ND;
    int n = loc / DD, d = loc % DD;
    int pb = ((NL - 1) & 1) * 2 * DD + gi * DD;
    float s = g_sum[pb + d];
    float q = g_sumsq[pb + d];
    float mu = s * (1.0f / NN);
    float var = q * (1.0f / NN) - mu * mu;
    float rstd = rsqrtf(var + 1e-5f);
    float v = (g_h2[idx] - mu) * rstd * gamma_l[d] + beta_l[d];
    (gi ? nrep1 : nrep0)[loc] = v;
    int b = (gi ? batch1 : batch0)[n];
    atomicAdd(&g_gsum[((size_t)gi * NG + b) * DD + d], v);
    if (d == 0) atomicAdd(&g_gcnt[gi * NG + b], 1.0f);
}

__global__ void k_pred(const float* __restrict__ predW,
                       const float* __restrict__ predb,
                       float* __restrict__ grep0, float* __restrict__ pred0,
                       float* __restrict__ grep1, float* __restrict__ pred1) {
    int g = blockIdx.x;
    int gi = g >= NG;
    int gl = g - gi * NG;
    float* grep = gi ? grep1 : grep0;
    float* pred = gi ? pred1 : pred0;
    __shared__ float rep[DD];
    float inv = 1.0f / fmaxf(g_gcnt[g], 1.0f);
    for (int d = threadIdx.x; d < DD; d += blockDim.x) {
        float v = g_gsum[(size_t)g * DD + d] * inv;
        rep[d] = v;
        grep[gl * DD + d] = v;
    }
    __syncthreads();
    if (threadIdx.x < NT) {
        int t = threadIdx.x;
        float acc = predb[t];
        for (int d = 0; d < DD; ++d) acc += rep[d] * predW[d * NT + t];
        pred[gl * NT + t] = acc;
    }
}

// ---------------- host orchestration ---------------------------------------

extern "C" void kernel_launch(void* const* d_in, const int* in_sizes, int n_in,
                              void* d_out, int out_size) {
    const int*   x      = (const int*)d_in[0];
    const int*   ei     = (const int*)d_in[1];
    const int*   ea     = (const int*)d_in[2];
    const int*   batch  = (const int*)d_in[3];
    const int*   x1     = (const int*)d_in[4];
    const int*   ei1    = (const int*)d_in[5];
    const int*   ea1    = (const int*)d_in[6];
    const int*   batch1 = (const int*)d_in[7];
    const float* xemb1  = (const float*)d_in[8];
    const float* xemb2  = (const float*)d_in[9];
    const float* eemb1  = (const float*)d_in[10];
    const float* eemb2  = (const float*)d_in[11];
    const float* W1     = (const float*)d_in[12];
    const float* b1     = (const float*)d_in[13];
    const float* W2     = (const float*)d_in[14];
    const float* b2     = (const float*)d_in[15];
    const float* gamma  = (const float*)d_in[16];
    const float* beta   = (const float*)d_in[17];
    const float* predW  = (const float*)d_in[18];
    const float* predb  = (const float*)d_in[19];

    cudaFuncSetAttribute((const void*)k_mgemm<128, 0>,
                         cudaFuncAttributeMaxDynamicSharedMemorySize, SMEM_128);
    cudaFuncSetAttribute((const void*)k_mgemm<128, 1>,
                         cudaFuncAttributeMaxDynamicSharedMemorySize, SMEM_128);
    cudaFuncSetAttribute((const void*)k_mgemm<64, 1>,
                         cudaFuncAttributeMaxDynamicSharedMemorySize, SMEM_64);

    float* out = (float*)d_out;
    float* pred0 = out;
    float* grep0 = out + NG * NT;
    float* nrep0 = out + NG * NT + NG * DD;
    float* pred1 = out + NG * NT + NG * DD + (size_t)NN * DD;
    float* grep1 = pred1 + NG * NT;
    float* nrep1 = pred1 + NG * NT + NG * DD;

    const int BLK = 256;
    const int GRID_2ND = (2 * ND + BLK - 1) / BLK;
    const int GRID_2NE = (2 * NE + BLK - 1) / BLK;
    const int GRID_M2 = M2PAD / 128;  // 782
    const int GRID_AGG = (2 * NN * 75 + BLK - 1) / BLK;
    const int GRID_ZP = (2 * ZR1 + 2 * ZR2 + BLK - 1) / BLK;

    // one-time builds
    k_split_w<<<(W1TOT + W2TOT + 255) / 256, 256>>>(W1, W2);   // + zero deg
    k_count<<<GRID_2NE, BLK>>>(ei, ei1);
    k_scan<<<2, 1024>>>();
    k_fill<<<GRID_2NE, BLK>>>(ei, ea, ei1, ea1);
    k_zero_pad<<<GRID_ZP, BLK>>>();
    k_init<<<GRID_2ND, BLK>>>(x, x1, xemb1, xemb2);

    for (int l = 0; l < NL; ++l) {
        const float* e1l = eemb1 + (size_t)l * NUM_BOND * DD;
        const float* e2l = eemb2 + (size_t)l * NUM_DIR * DD;
        const float* gp = gamma + (size_t)(l > 0 ? l - 1 : 0) * DD;
        const float* bp = beta  + (size_t)(l > 0 ? l - 1 : 0) * DD;

        k_aggregate<<<GRID_AGG, BLK>>>(l, e1l, e2l, gp, bp);

        k_mgemm<128, 0><<<dim3(N1P / 128, GRID_M2), 256, SMEM_128>>>(
            l, b1 + (size_t)l * DD2, 0);
        k_mgemm<128, 1><<<dim3(2, GRID_M2), 256, SMEM_128>>>(
            l, b2 + (size_t)l * DD, 0);
        k_mgemm<64, 1><<<dim3(1, GRID_M2), 256, SMEM_64>>>(
            l, b2 + (size_t)l * DD, 256);
    }

    k_bnpool<<<GRID_2ND, BLK>>>(gamma + (size_t)(NL - 1) * DD,
                                beta + (size_t)(NL - 1) * DD,
                                batch, batch1, nrep0, nrep1);
    k_pred<<<2 * NG, 128>>>(predW, predb, grep0, pred0, grep1, pred1);
}

// round 15
// speedup vs baseline: 1.6049x; 1.0160x over previous
#include <cuda_runtime.h>
#include <cuda_bf16.h>
#include <cstdint>

// Problem constants
#define NN   50000
#define NE   100000
#define NG   2000
#define DD   300
#define DD2  600
#define NL   5
#define NT   10
#define NUM_BOND 6
#define NUM_DIR  3
#define ND   (NN*DD)
#define ED   (NE*DD)

// Padded GEMM dims (per graph), both graphs stacked along M
#define MPAD  50048          // 391 * 128
#define M2PAD (2*MPAD)       // 100096
#define K1P  320             // GEMM1 K (300 padded)
#define K2P  608             // GEMM2 K / T row stride (600 padded)
#define N1P  640             // GEMM1 N sweep
#define N2P  320             // GEMM2 N (300 padded): 128+128+64

// smem geometry
#define RS     80
#define MATB   (128*RS)

// ---------------- scratch ---------------------------------------------------
__device__ float g_h[2*ND];      // initial features only (layer 0 input)
__device__ float g_h2[2*ND];     // raw GEMM2 output (pre-BN)
__device__ __nv_bfloat16 g_Ahi[(size_t)M2PAD * K1P];
__device__ __nv_bfloat16 g_Alo[(size_t)M2PAD * K1P];
__device__ __nv_bfloat16 g_Thi[(size_t)M2PAD * K2P];
__device__ __nv_bfloat16 g_Tlo[(size_t)M2PAD * K2P];
__device__ __nv_bfloat16 g_W1hi[NL * N1P * K1P];
__device__ __nv_bfloat16 g_W1lo[NL * N1P * K1P];
__device__ __nv_bfloat16 g_W2hi[NL * N2P * K2P];
__device__ __nv_bfloat16 g_W2lo[NL * N2P * K2P];
__device__ float g_sum[2*DD], g_sumsq[2*DD];       // single-buffered stats
__device__ float g_scale[2*DD], g_shift[2*DD];     // precomputed BN apply table
__device__ float g_gsum[2*NG*DD], g_gcnt[2*NG];
// CSR (built once per call; layer-invariant)
__device__ int g_deg[2*NN];
__device__ int g_off[2*(NN+1)];
__device__ int g_cur[2*NN];
__device__ int g_elist[2*NE];     // src | (combo<<17), combo = a0*3+a1

// ---------------- PTX helpers (baseline ISA only) ----------------------------
__device__ __forceinline__ uint32_t smem_to_u32(const void* p) {
    uint32_t a;
    asm("{ .reg .u64 t; cvta.to.shared.u64 t, %1; cvt.u32.u64 %0, t; }" : "=r"(a) : "l"(p));
    return a;
}

#define LDMX4(r, addr) \
    asm volatile("ldmatrix.sync.aligned.m8n8.x4.shared.b16 {%0,%1,%2,%3}, [%4];" \
        : "=r"((r)[0]), "=r"((r)[1]), "=r"((r)[2]), "=r"((r)[3]) : "r"(addr))

#define MMA_BF16(d, a, b) \
    asm volatile("mma.sync.aligned.m16n8k16.row.col.f32.bf16.bf16.f32 " \
        "{%0,%1,%2,%3}, {%4,%5,%6,%7}, {%8,%9}, {%0,%1,%2,%3};" \
        : "+f"((d)[0]), "+f"((d)[1]), "+f"((d)[2]), "+f"((d)[3]) \
        : "r"((a)[0]), "r"((a)[1]), "r"((a)[2]), "r"((a)[3]), \
          "r"((b)[0]), "r"((b)[1]))

#define CP_ASYNC16(dst, src) \
    asm volatile("cp.async.ca.shared.global [%0], [%1], 16;" :: "r"(dst), "l"(src) : "memory")
#define CP_COMMIT() asm volatile("cp.async.commit_group;" ::: "memory")
#define CP_WAIT1()  asm volatile("cp.async.wait_group 1;" ::: "memory")
#define CP_WAIT0()  asm volatile("cp.async.wait_group 0;" ::: "memory")

// ---------------- one-time build kernels -------------------------------------

#define W1TOT (NL * N1P * K1P)
#define W2TOT (NL * N2P * K2P)
__global__ void k_split_w(const float* __restrict__ W1, const float* __restrict__ W2) {
    int idx = blockIdx.x * blockDim.x + threadIdx.x;
    if (idx < 2 * NN) g_deg[idx] = 0;
    if (idx < W1TOT) {
        int l = idx / (N1P * K1P);
        int rem = idx - l * (N1P * K1P);
        int n = rem / K1P, k = rem - n * K1P;
        const float* src = W1 + (size_t)l * DD * DD2;
        float v = (n < DD2 && k < DD) ? src[(size_t)k * DD2 + n] : 0.f;
        __nv_bfloat16 h = __float2bfloat16(v);
        g_W1hi[idx] = h;
        g_W1lo[idx] = __float2bfloat16(v - __bfloat162float(h));
    } else if (idx < W1TOT + W2TOT) {
        int j = idx - W1TOT;
        int l = j / (N2P * K2P);
        int rem = j - l * (N2P * K2P);
        int n = rem / K2P, k = rem - n * K2P;
        const float* src = W2 + (size_t)l * DD2 * DD;
        float v = (n < DD && k < DD2) ? src[(size_t)k * DD + n] : 0.f;
        __nv_bfloat16 h = __float2bfloat16(v);
        g_W2hi[j] = h;
        g_W2lo[j] = __float2bfloat16(v - __bfloat162float(h));
    }
}

__global__ void k_count(const int* __restrict__ ei0, const int* __restrict__ ei1) {
    int idx = blockIdx.x * blockDim.x + threadIdx.x;
    if (idx >= 2 * NE) return;
    int gi = idx >= NE;
    int e = idx - gi * NE;
    const int* ei = gi ? ei1 : ei0;
    atomicAdd(&g_deg[gi * NN + ei[NE + e]], 1);
}

__global__ void __launch_bounds__(1024) k_scan() {
    int gi = blockIdx.x;
    const int* deg = g_deg + gi * NN;
    int* off = g_off + gi * (NN + 1);
    int* cur = g_cur + gi * NN;
    __shared__ int partial[1024];
    const int CH = (NN + 1023) / 1024;
    int t = threadIdx.x;
    int base = t * CH;
    int s = 0;
    for (int i = 0; i < CH; i++) {
        int u = base + i;
        if (u < NN) s += deg[u];
    }
    partial[t] = s;
    __syncthreads();
    if (t == 0) {
        int acc = 0;
        for (int i = 0; i < 1024; i++) { int tmp = partial[i]; partial[i] = acc; acc += tmp; }
    }
    __syncthreads();
    int run = partial[t];
    for (int i = 0; i < CH; i++) {
        int u = base + i;
        if (u < NN) { off[u] = run; cur[u] = run; run += deg[u]; }
    }
    if (t == 0) off[NN] = NE;
}

__global__ void k_fill(const int* __restrict__ ei0, const int* __restrict__ ea0,
                       const int* __restrict__ ei1, const int* __restrict__ ea1) {
    int idx = blockIdx.x * blockDim.x + threadIdx.x;
    if (idx >= 2 * NE) return;
    int gi = idx >= NE;
    int e = idx - gi * NE;
    const int* ei = gi ? ei1 : ei0;
    const int* ea = gi ? ea1 : ea0;
    int src = ei[e];
    int dst = ei[NE + e];
    int a0 = ea[2 * e], a1 = ea[2 * e + 1];
    int pos = atomicAdd(&g_cur[gi * NN + dst], 1);
    g_elist[gi * NE + pos] = src | ((a0 * 3 + a1) << 17);
}

// zero pad regions of Ahi/Alo once per call
#define ZR1 (M2PAD*20)
#define ZR2 (2*48*320)
__global__ void k_zero_pad() {
    int idx = blockIdx.x * blockDim.x + threadIdx.x;
    __nv_bfloat16 z = __float2bfloat16(0.f);
    if (idx < 2 * ZR1) {
        __nv_bfloat16* arr = idx < ZR1 ? g_Ahi : g_Alo;
        int j = idx < ZR1 ? idx : idx - ZR1;
        int r = j / 20, c = 300 + j % 20;
        arr[(size_t)r * K1P + c] = z;
    } else {
        int j = idx - 2 * ZR1;
        if (j >= 2 * ZR2) return;
        __nv_bfloat16* arr = j < ZR2 ? g_Ahi : g_Alo;
        if (j >= ZR2) j -= ZR2;
        int gi = j >= (48 * 320);
        if (gi) j -= 48 * 320;
        int r = gi * MPAD + NN + j / 320;
        int c = j % 320;
        arr[(size_t)r * K1P + c] = z;
    }
}

// ---------------- per-layer kernels ------------------------------------------

__global__ void k_init(const int* __restrict__ x0, const int* __restrict__ x1,
                       const float* __restrict__ xemb1,
                       const float* __restrict__ xemb2) {
    int idx = blockIdx.x * blockDim.x + threadIdx.x;
    if (idx < 2 * NG * DD) g_gsum[idx] = 0.f;
    if (idx < 2 * NG) g_gcnt[idx] = 0.f;
    if (idx < 2 * DD) { g_sum[idx] = 0.f; g_sumsq[idx] = 0.f; }
    if (idx >= 2 * ND) return;
    int gi = idx >= ND;
    int loc = idx - gi * ND;
    int n = loc / DD, d = loc - n * DD;
    const int* xs = gi ? x1 : x0;
    int a = xs[2 * n], c = xs[2 * n + 1];
    g_h[idx] = xemb1[a * DD + d] + xemb2[c * DD + d];
}

// tiny per-layer kernel: stats -> scale/shift table; re-zero stats in place
__global__ void k_bnprep(const float* __restrict__ gamma_l,
                         const float* __restrict__ beta_l) {
    int idx = blockIdx.x * blockDim.x + threadIdx.x;
    if (idx >= 2 * DD) return;
    int d = idx >= DD ? idx - DD : idx;
    float s = g_sum[idx];
    float q = g_sumsq[idx];
    float mu = s * (1.0f / NN);
    float var = q * (1.0f / NN) - mu * mu;
    float rstd = rsqrtf(var + 1e-5f);
    float sc = rstd * gamma_l[d];
    g_scale[idx] = sc;
    g_shift[idx] = beta_l[d] - mu * sc;
    g_sum[idx] = 0.f;
    g_sumsq[idx] = 0.f;
}

// CSR aggregate with fused BN-apply-on-read (layers > 0) and bf16 split store.
// l==0: src = g_h raw. l>0: src = relu(h2*scale + shift) via precomputed table.
__global__ void k_aggregate(int l,
                            const float* __restrict__ e1l,
                            const float* __restrict__ e2l) {
    int idx = blockIdx.x * blockDim.x + threadIdx.x;
    const int TPG = NN * 75;
    if (idx >= 2 * TPG) return;
    int gi = idx >= TPG;
    int rem = idx - gi * TPG;
    int n = rem / 75, dq = rem - n * 75;
    int d = dq * 4;
    const float* src = (l == 0) ? (g_h + (size_t)gi * ND) : (g_h2 + (size_t)gi * ND);

    float4 scale, shift;
    if (l == 0) {
        scale = make_float4(1.f, 1.f, 1.f, 1.f);
        shift = make_float4(0.f, 0.f, 0.f, 0.f);
    } else {
        scale = *(const float4*)&g_scale[gi * DD + d];
        shift = *(const float4*)&g_shift[gi * DD + d];
    }

    auto ldsrc = [&](int node) -> float4 {
        float4 r = *(const float4*)&src[(size_t)node * DD + d];
        if (l > 0) {
            r.x = fmaxf(fmaf(r.x, scale.x, shift.x), 0.f);
            r.y = fmaxf(fmaf(r.y, scale.y, shift.y), 0.f);
            r.z = fmaxf(fmaf(r.z, scale.z, shift.z), 0.f);
            r.w = fmaxf(fmaf(r.w, scale.w, shift.w), 0.f);
        }
        return r;
    };

    float4 v = ldsrc(n);
    float4 s1 = *(const float4*)&e1l[4 * DD + d];
    float4 s2 = *(const float4*)&e2l[d];
    v.x += s1.x + s2.x; v.y += s1.y + s2.y;
    v.z += s1.z + s2.z; v.w += s1.w + s2.w;

    int beg = g_off[gi * (NN + 1) + n];
    int end = g_off[gi * (NN + 1) + n + 1];
    const int* el = g_elist + gi * NE;
    for (int j = beg; j < end; j++) {
        int p = el[j];
        int srcn = p & 0x1FFFF;
        int c = p >> 17;
        int a0 = c / 3, a1 = c - a0 * 3;
        float4 hv = ldsrc(srcn);
        float4 t1 = *(const float4*)&e1l[a0 * DD + d];
        float4 t2 = *(const float4*)&e2l[a1 * DD + d];
        v.x += hv.x + t1.x + t2.x;
        v.y += hv.y + t1.y + t2.y;
        v.z += hv.z + t1.z + t2.z;
        v.w += hv.w + t1.w + t2.w;
    }

    union { __nv_bfloat162 b2[2]; uint2 u; } uh, ul;
    __nv_bfloat16 h0 = __float2bfloat16(v.x), h1 = __float2bfloat16(v.y);
    __nv_bfloat16 h2 = __float2bfloat16(v.z), h3 = __float2bfloat16(v.w);
    uh.b2[0].x = h0; uh.b2[0].y = h1; uh.b2[1].x = h2; uh.b2[1].y = h3;
    ul.b2[0].x = __float2bfloat16(v.x - __bfloat162float(h0));
    ul.b2[0].y = __float2bfloat16(v.y - __bfloat162float(h1));
    ul.b2[1].x = __float2bfloat16(v.z - __bfloat162float(h2));
    ul.b2[1].y = __float2bfloat16(v.w - __bfloat162float(h3));
    size_t m = (size_t)(gi * MPAD + n);
    *(uint2*)&g_Ahi[m * K1P + d] = uh.u;
    *(uint2*)&g_Alo[m * K1P + d] = ul.u;
}

// ---------------- mma.sync bf16-split GEMM (unchanged mainloop) --------------
template <int TN, int MODE>
__global__ void __launch_bounds__(256)
k_mgemm(int l, const float* __restrict__ bias, int colbase) {
    constexpr int KPAD = MODE ? K2P : K1P;
    constexpr int NC   = MODE ? DD  : DD2;
    constexpr int NCHUNK = KPAD / 32;
    constexpr int JT = TN / 32;
    constexpr int BMATB = TN * RS;
    constexpr int STAGEB = 2 * MATB + 2 * BMATB;
    const __nv_bfloat16* __restrict__ Ahi = MODE ? g_Thi : g_Ahi;
    const __nv_bfloat16* __restrict__ Alo = MODE ? g_Tlo : g_Alo;
    const __nv_bfloat16* __restrict__ Bhi =
        MODE ? (g_W2hi + (size_t)l * N2P * K2P) : (g_W1hi + (size_t)l * N1P * K1P);
    const __nv_bfloat16* __restrict__ Blo =
        MODE ? (g_W2lo + (size_t)l * N2P * K2P) : (g_W1lo + (size_t)l * N1P * K1P);

    extern __shared__ __align__(16) char smem[];
    const uint32_t sbase = smem_to_u32(smem);
    const int tid = threadIdx.x;
    const int wid = tid >> 5;
    const int lane = tid & 31;
    const int row0 = blockIdx.y * 128;
    const int col0 = colbase + blockIdx.x * TN;
    const int wm = wid & 1;
    const int wn = wid >> 1;
    const int lr = lane & 15;
    const int lc = lane >> 4;

    auto issue = [&](int c) {
        const int buf = c & 1;
        const int k0 = c * 32;
        #pragma unroll
        for (int i = 0; i < 4; i++) {
            int u = tid + i * 256;
            int mat = u >> 9;
            int r = (u >> 2) & 127;
            int c16 = u & 3;
            const __nv_bfloat16* gp = (mat ? Alo : Ahi)
                + (size_t)(row0 + r) * KPAD + k0 + c16 * 8;
            uint32_t dst = sbase + buf * STAGEB + mat * MATB + r * RS + c16 * 16;
            CP_ASYNC16(dst, gp);
        }
        #pragma unroll
        for (int i = 0; i < TN / 32; i++) {
            int u = tid + i * 256;
            int mat = u / (4 * TN);
            int w = u - mat * (4 * TN);
            int r = w >> 2;
            int c16 = w & 3;
            const __nv_bfloat16* gp = (mat ? Blo : Bhi)
                + (size_t)(col0 + r) * KPAD + k0 + c16 * 8;
            uint32_t dst = sbase + buf * STAGEB + 2 * MATB + mat * BMATB
                         + r * RS + c16 * 16;
            CP_ASYNC16(dst, gp);
        }
        CP_COMMIT();
    };

    float acc[4][JT][4] = {};

    issue(0);
    for (int c = 0; c < NCHUNK; c++) {
        if (c + 1 < NCHUNK) { issue(c + 1); CP_WAIT1(); }
        else                { CP_WAIT0(); }
        __syncthreads();
        const uint32_t sb = sbase + (c & 1) * STAGEB;
        #pragma unroll
        for (int s = 0; s < 2; s++) {
            uint32_t ahi[4][4], alo[4][4], bhi[JT][2], blo[JT][2];
            #pragma unroll
            for (int i = 0; i < 4; i++) {
                uint32_t ra = sb + (wm * 64 + i * 16 + lr) * RS + s * 32 + lc * 16;
                LDMX4(ahi[i], ra);
                LDMX4(alo[i], ra + MATB);
            }
            #pragma unroll
            for (int jp = 0; jp < JT / 2; jp++) {
                uint32_t rb = sb + 2 * MATB + (wn * (TN / 4) + jp * 16 + lr) * RS
                            + s * 32 + lc * 16;
                uint32_t t[4];
                LDMX4(t, rb);
                bhi[2 * jp][0] = t[0]; bhi[2 * jp + 1][0] = t[1];
                bhi[2 * jp][1] = t[2]; bhi[2 * jp + 1][1] = t[3];
                LDMX4(t, rb + BMATB);
                blo[2 * jp][0] = t[0]; blo[2 * jp + 1][0] = t[1];
                blo[2 * jp][1] = t[2]; blo[2 * jp + 1][1] = t[3];
            }
            #pragma unroll
            for (int i = 0; i < 4; i++)
                #pragma unroll
                for (int j = 0; j < JT; j++) {
                    MMA_BF16(acc[i][j], ahi[i], bhi[j]);
                    MMA_BF16(acc[i][j], ahi[i], blo[j]);
                    MMA_BF16(acc[i][j], alo[i], bhi[j]);
                }
        }
        __syncthreads();
    }

    if (MODE == 0) {
        #pragma unroll
        for (int i = 0; i < 4; i++) {
            #pragma unroll
            for (int j = 0; j < JT; j++) {
                #pragma unroll
                for (int h = 0; h < 2; h++) {
                    int m = row0 + wm * 64 + i * 16 + (lane >> 2) + h * 8;
                    int n = col0 + wn * (TN / 4) + j * 8 + (lane & 3) * 2;
                    if (n >= K2P) continue;
                    float v0 = acc[i][j][h * 2];
                    float v1 = acc[i][j][h * 2 + 1];
                    if (n < NC) {
                        v0 = fmaxf(v0 + bias[n], 0.f);
                        v1 = fmaxf(v1 + bias[n + 1], 0.f);
                    } else { v0 = 0.f; v1 = 0.f; }
                    __nv_bfloat16 h0 = __float2bfloat16(v0);
                    __nv_bfloat16 h1 = __float2bfloat16(v1);
                    __nv_bfloat16 l0 = __float2bfloat16(v0 - __bfloat162float(h0));
                    __nv_bfloat16 l1 = __float2bfloat16(v1 - __bfloat162float(h1));
                    size_t o = (size_t)m * K2P + n;
                    __nv_bfloat162 th; th.x = h0; th.y = h1;
                    __nv_bfloat162 tl; tl.x = l0; tl.y = l1;
                    *(__nv_bfloat162*)&g_Thi[o] = th;
                    *(__nv_bfloat162*)&g_Tlo[o] = tl;
                }
            }
        }
    } else {
        const int gi = row0 >= MPAD;
        const int sb2 = gi * DD;
        float cs[2 * JT], cq[2 * JT];
        #pragma unroll
        for (int k = 0; k < 2 * JT; k++) { cs[k] = 0.f; cq[k] = 0.f; }
        #pragma unroll
        for (int i = 0; i < 4; i++) {
            #pragma unroll
            for (int j = 0; j < JT; j++) {
                #pragma unroll
                for (int h = 0; h < 2; h++) {
                    int m = row0 + wm * 64 + i * 16 + (lane >> 2) + h * 8;
                    int node = m - gi * MPAD;
                    int n = col0 + wn * (TN / 4) + j * 8 + (lane & 3) * 2;
                    if (node < NN && n < NC) {
                        float v0 = acc[i][j][h * 2]     + bias[n];
                        float v1 = acc[i][j][h * 2 + 1] + bias[n + 1];
                        float2 v; v.x = v0; v.y = v1;
                        *(float2*)&g_h2[((size_t)gi * NN + node) * DD + n] = v;
                        cs[j * 2]     += v0; cq[j * 2]     += v0 * v0;
                        cs[j * 2 + 1] += v1; cq[j * 2 + 1] += v1 * v1;
                    }
                }
            }
        }
        #pragma unroll
        for (int off = 4; off < 32; off <<= 1) {
            #pragma unroll
            for (int k = 0; k < 2 * JT; k++) {
                cs[k] += __shfl_xor_sync(0xffffffffu, cs[k], off);
                cq[k] += __shfl_xor_sync(0xffffffffu, cq[k], off);
            }
        }
        if ((lane >> 2) == 0) {
            #pragma unroll
            for (int k = 0; k < 2 * JT; k++) {
                int n = col0 + wn * (TN / 4) + (k >> 1) * 8 + (lane & 3) * 2 + (k & 1);
                if (n < NC) {
                    atomicAdd(&g_sum[sb2 + n], cs[k]);
                    atomicAdd(&g_sumsq[sb2 + n], cq[k]);
                }
            }
        }
    }
}

#define SMEM_128 (2 * (2 * MATB + 2 * 128 * RS))   // 81920
#define SMEM_64  (2 * (2 * MATB + 2 * 64 * RS))    // 61440

// ---------------- final BN + pool (fused) + pred ------------------------------

// last layer: nrep = h2*scale + shift (table; no relu); pool atomics fused
__global__ void k_bnpool(const int* __restrict__ batch0,
                         const int* __restrict__ batch1,
                         float* __restrict__ nrep0,
                         float* __restrict__ nrep1) {
    int idx = blockIdx.x * blockDim.x + threadIdx.x;
    if (idx >= 2 * ND) return;
    int gi = idx >= ND;
    int loc = idx - gi * ND;
    int n = loc / DD, d = loc % DD;
    float v = fmaf(g_h2[idx], g_scale[gi * DD + d], g_shift[gi * DD + d]);
    (gi ? nrep1 : nrep0)[loc] = v;
    int b = (gi ? batch1 : batch0)[n];
    atomicAdd(&g_gsum[((size_t)gi * NG + b) * DD + d], v);
    if (d == 0) atomicAdd(&g_gcnt[gi * NG + b], 1.0f);
}

__global__ void k_pred(const float* __restrict__ predW,
                       const float* __restrict__ predb,
                       float* __restrict__ grep0, float* __restrict__ pred0,
                       float* __restrict__ grep1, float* __restrict__ pred1) {
    int g = blockIdx.x;
    int gi = g >= NG;
    int gl = g - gi * NG;
    float* grep = gi ? grep1 : grep0;
    float* pred = gi ? pred1 : pred0;
    __shared__ float rep[DD];
    float inv = 1.0f / fmaxf(g_gcnt[g], 1.0f);
    for (int d = threadIdx.x; d < DD; d += blockDim.x) {
        float v = g_gsum[(size_t)g * DD + d] * inv;
        rep[d] = v;
        grep[gl * DD + d] = v;
    }
    __syncthreads();
    if (threadIdx.x < NT) {
        int t = threadIdx.x;
        float acc = predb[t];
        for (int d = 0; d < DD; ++d) acc += rep[d] * predW[d * NT + t];
        pred[gl * NT + t] = acc;
    }
}

// ---------------- host orchestration ---------------------------------------

extern "C" void kernel_launch(void* const* d_in, const int* in_sizes, int n_in,
                              void* d_out, int out_size) {
    const int*   x      = (const int*)d_in[0];
    const int*   ei     = (const int*)d_in[1];
    const int*   ea     = (const int*)d_in[2];
    const int*   batch  = (const int*)d_in[3];
    const int*   x1     = (const int*)d_in[4];
    const int*   ei1    = (const int*)d_in[5];
    const int*   ea1    = (const int*)d_in[6];
    const int*   batch1 = (const int*)d_in[7];
    const float* xemb1  = (const float*)d_in[8];
    const float* xemb2  = (const float*)d_in[9];
    const float* eemb1  = (const float*)d_in[10];
    const float* eemb2  = (const float*)d_in[11];
    const float* W1     = (const float*)d_in[12];
    const float* b1     = (const float*)d_in[13];
    const float* W2     = (const float*)d_in[14];
    const float* b2     = (const float*)d_in[15];
    const float* gamma  = (const float*)d_in[16];
    const float* beta   = (const float*)d_in[17];
    const float* predW  = (const float*)d_in[18];
    const float* predb  = (const float*)d_in[19];

    cudaFuncSetAttribute((const void*)k_mgemm<128, 0>,
                         cudaFuncAttributeMaxDynamicSharedMemorySize, SMEM_128);
    cudaFuncSetAttribute((const void*)k_mgemm<128, 1>,
                         cudaFuncAttributeMaxDynamicSharedMemorySize, SMEM_128);
    cudaFuncSetAttribute((const void*)k_mgemm<64, 1>,
                         cudaFuncAttributeMaxDynamicSharedMemorySize, SMEM_64);

    float* out = (float*)d_out;
    float* pred0 = out;
    float* grep0 = out + NG * NT;
    float* nrep0 = out + NG * NT + NG * DD;
    float* pred1 = out + NG * NT + NG * DD + (size_t)NN * DD;
    float* grep1 = pred1 + NG * NT;
    float* nrep1 = pred1 + NG * NT + NG * DD;

    const int BLK = 256;
    const int GRID_2ND = (2 * ND + BLK - 1) / BLK;
    const int GRID_2NE = (2 * NE + BLK - 1) / BLK;
    const int GRID_M2 = M2PAD / 128;  // 782
    const int GRID_AGG = (2 * NN * 75 + BLK - 1) / BLK;
    const int GRID_ZP = (2 * ZR1 + 2 * ZR2 + BLK - 1) / BLK;

    // one-time builds
    k_split_w<<<(W1TOT + W2TOT + 255) / 256, 256>>>(W1, W2);   // + zero deg
    k_count<<<GRID_2NE, BLK>>>(ei, ei1);
    k_scan<<<2, 1024>>>();
    k_fill<<<GRID_2NE, BLK>>>(ei, ea, ei1, ea1);
    k_zero_pad<<<GRID_ZP, BLK>>>();
    k_init<<<GRID_2ND, BLK>>>(x, x1, xemb1, xemb2);

    for (int l = 0; l < NL; ++l) {
        const float* e1l = eemb1 + (size_t)l * NUM_BOND * DD;
        const float* e2l = eemb2 + (size_t)l * NUM_DIR * DD;

        if (l > 0)
            k_bnprep<<<3, 256>>>(gamma + (size_t)(l - 1) * DD,
                                 beta + (size_t)(l - 1) * DD);

        k_aggregate<<<GRID_AGG, BLK>>>(l, e1l, e2l);

        k_mgemm<128, 0><<<dim3(N1P / 128, GRID_M2), 256, SMEM_128>>>(
            l, b1 + (size_t)l * DD2, 0);
        k_mgemm<128, 1><<<dim3(2, GRID_M2), 256, SMEM_128>>>(
            l, b2 + (size_t)l * DD, 0);
        k_mgemm<64, 1><<<dim3(1, GRID_M2), 256, SMEM_64>>>(
            l, b2 + (size_t)l * DD, 256);
    }

    k_bnprep<<<3, 256>>>(gamma + (size_t)(NL - 1) * DD,
                         beta + (size_t)(NL - 1) * DD);
    k_bnpool<<<GRID_2ND, BLK>>>(batch, batch1, nrep0, nrep1);
    k_pred<<<2 * NG, 128>>>(predW, predb, grep0, pred0, grep1, pred1);
}

// round 17
// speedup vs baseline: 1.6922x; 1.0544x over previous
#include <cuda_runtime.h>
#include <cuda_bf16.h>
#include <cstdint>

// Problem constants
#define NN   50000
#define NE   100000
#define NG   2000
#define DD   300
#define DD2  600
#define NL   5
#define NT   10
#define NUM_BOND 6
#define NUM_DIR  3
#define ND   (NN*DD)
#define ED   (NE*DD)

// Padded GEMM dims (per graph), both graphs stacked along M in scratch
#define MPAD  50048          // 391 * 128
#define M2PAD (2*MPAD)
#define K1P  320             // GEMM1 K (300 padded)
#define K2P  608             // GEMM2 K / T row stride (600 padded)
#define N1P  640             // GEMM1 N sweep
#define N2P  320             // GEMM2 N (300 padded): 128+128+64

// smem geometry
#define RS     80
#define MATB   (128*RS)

// ---------------- scratch ---------------------------------------------------
__device__ float g_h[2*ND];
__device__ float g_h2[2*ND];
__device__ __nv_bfloat16 g_Ahi[(size_t)M2PAD * K1P];
__device__ __nv_bfloat16 g_Alo[(size_t)M2PAD * K1P];
__device__ __nv_bfloat16 g_Thi[(size_t)M2PAD * K2P];
__device__ __nv_bfloat16 g_Tlo[(size_t)M2PAD * K2P];
__device__ __nv_bfloat16 g_W1hi[NL * N1P * K1P];
__device__ __nv_bfloat16 g_W1lo[NL * N1P * K1P];
__device__ __nv_bfloat16 g_W2hi[NL * N2P * K2P];
__device__ __nv_bfloat16 g_W2lo[NL * N2P * K2P];
__device__ float g_sum[2*DD], g_sumsq[2*DD];
__device__ float g_scale[2*DD], g_shift[2*DD];
__device__ float g_gsum[2*NG*DD], g_gcnt[2*NG];
// CSR (layer-invariant)
__device__ int g_deg[2*NN];
__device__ int g_off[2*(NN+1)];
__device__ int g_cur[2*NN];
__device__ int g_elist[2*NE];

// ---------------- PTX helpers ------------------------------------------------
__device__ __forceinline__ uint32_t smem_to_u32(const void* p) {
    uint32_t a;
    asm("{ .reg .u64 t; cvta.to.shared.u64 t, %1; cvt.u32.u64 %0, t; }" : "=r"(a) : "l"(p));
    return a;
}

#define LDMX4(r, addr) \
    asm volatile("ldmatrix.sync.aligned.m8n8.x4.shared.b16 {%0,%1,%2,%3}, [%4];" \
        : "=r"((r)[0]), "=r"((r)[1]), "=r"((r)[2]), "=r"((r)[3]) : "r"(addr))

#define MMA_BF16(d, a, b) \
    asm volatile("mma.sync.aligned.m16n8k16.row.col.f32.bf16.bf16.f32 " \
        "{%0,%1,%2,%3}, {%4,%5,%6,%7}, {%8,%9}, {%0,%1,%2,%3};" \
        : "+f"((d)[0]), "+f"((d)[1]), "+f"((d)[2]), "+f"((d)[3]) \
        : "r"((a)[0]), "r"((a)[1]), "r"((a)[2]), "r"((a)[3]), \
          "r"((b)[0]), "r"((b)[1]))

#define CP_ASYNC16(dst, src) \
    asm volatile("cp.async.ca.shared.global [%0], [%1], 16;" :: "r"(dst), "l"(src) : "memory")
#define CP_COMMIT() asm volatile("cp.async.commit_group;" ::: "memory")
#define CP_WAIT1()  asm volatile("cp.async.wait_group 1;" ::: "memory")
#define CP_WAIT0()  asm volatile("cp.async.wait_group 0;" ::: "memory")

// ---------------- one-time build kernels -------------------------------------

#define W1TOT (NL * N1P * K1P)
#define W2TOT (NL * N2P * K2P)
__global__ void k_split_w(const float* __restrict__ W1, const float* __restrict__ W2) {
    int idx = blockIdx.x * blockDim.x + threadIdx.x;
    if (idx < 2 * NN) g_deg[idx] = 0;
    if (idx < W1TOT) {
        int l = idx / (N1P * K1P);
        int rem = idx - l * (N1P * K1P);
        int n = rem / K1P, k = rem - n * K1P;
        const float* src = W1 + (size_t)l * DD * DD2;
        float v = (n < DD2 && k < DD) ? src[(size_t)k * DD2 + n] : 0.f;
        __nv_bfloat16 h = __float2bfloat16(v);
        g_W1hi[idx] = h;
        g_W1lo[idx] = __float2bfloat16(v - __bfloat162float(h));
    } else if (idx < W1TOT + W2TOT) {
        int j = idx - W1TOT;
        int l = j / (N2P * K2P);
        int rem = j - l * (N2P * K2P);
        int n = rem / K2P, k = rem - n * K2P;
        const float* src = W2 + (size_t)l * DD2 * DD;
        float v = (n < DD && k < DD2) ? src[(size_t)k * DD + n] : 0.f;
        __nv_bfloat16 h = __float2bfloat16(v);
        g_W2hi[j] = h;
        g_W2lo[j] = __float2bfloat16(v - __bfloat162float(h));
    }
}

__global__ void k_count(const int* __restrict__ ei0, const int* __restrict__ ei1) {
    int idx = blockIdx.x * blockDim.x + threadIdx.x;
    if (idx >= 2 * NE) return;
    int gi = idx >= NE;
    int e = idx - gi * NE;
    const int* ei = gi ? ei1 : ei0;
    atomicAdd(&g_deg[gi * NN + ei[NE + e]], 1);
}

__global__ void __launch_bounds__(1024) k_scan() {
    int gi = blockIdx.x;
    const int* deg = g_deg + gi * NN;
    int* off = g_off + gi * (NN + 1);
    int* cur = g_cur + gi * NN;
    __shared__ int partial[1024];
    const int CH = (NN + 1023) / 1024;
    int t = threadIdx.x;
    int base = t * CH;
    int s = 0;
    for (int i = 0; i < CH; i++) {
        int u = base + i;
        if (u < NN) s += deg[u];
    }
    partial[t] = s;
    __syncthreads();
    if (t == 0) {
        int acc = 0;
        for (int i = 0; i < 1024; i++) { int tmp = partial[i]; partial[i] = acc; acc += tmp; }
    }
    __syncthreads();
    int run = partial[t];
    for (int i = 0; i < CH; i++) {
        int u = base + i;
        if (u < NN) { off[u] = run; cur[u] = run; run += deg[u]; }
    }
    if (t == 0) off[NN] = NE;
}

__global__ void k_fill(const int* __restrict__ ei0, const int* __restrict__ ea0,
                       const int* __restrict__ ei1, const int* __restrict__ ea1) {
    int idx = blockIdx.x * blockDim.x + threadIdx.x;
    if (idx >= 2 * NE) return;
    int gi = idx >= NE;
    int e = idx - gi * NE;
    const int* ei = gi ? ei1 : ei0;
    const int* ea = gi ? ea1 : ea0;
    int src = ei[e];
    int dst = ei[NE + e];
    int a0 = ea[2 * e], a1 = ea[2 * e + 1];
    int pos = atomicAdd(&g_cur[gi * NN + dst], 1);
    g_elist[gi * NE + pos] = src | ((a0 * 3 + a1) << 17);
}

#define ZR1 (M2PAD*20)
#define ZR2 (2*48*320)
__global__ void k_zero_pad() {
    int idx = blockIdx.x * blockDim.x + threadIdx.x;
    __nv_bfloat16 z = __float2bfloat16(0.f);
    if (idx < 2 * ZR1) {
        __nv_bfloat16* arr = idx < ZR1 ? g_Ahi : g_Alo;
        int j = idx < ZR1 ? idx : idx - ZR1;
        int r = j / 20, c = 300 + j % 20;
        arr[(size_t)r * K1P + c] = z;
    } else {
        int j = idx - 2 * ZR1;
        if (j >= 2 * ZR2) return;
        __nv_bfloat16* arr = j < ZR2 ? g_Ahi : g_Alo;
        if (j >= ZR2) j -= ZR2;
        int gi = j >= (48 * 320);
        if (gi) j -= 48 * 320;
        int r = gi * MPAD + NN + j / 320;
        int c = j % 320;
        arr[(size_t)r * K1P + c] = z;
    }
}

__global__ void k_init(const int* __restrict__ x0, const int* __restrict__ x1,
                       const float* __restrict__ xemb1,
                       const float* __restrict__ xemb2) {
    int idx = blockIdx.x * blockDim.x + threadIdx.x;
    if (idx < 2 * NG * DD) g_gsum[idx] = 0.f;
    if (idx < 2 * NG) g_gcnt[idx] = 0.f;
    if (idx < 2 * DD) { g_sum[idx] = 0.f; g_sumsq[idx] = 0.f; }
    if (idx >= 2 * ND) return;
    int gi = idx >= ND;
    int loc = idx - gi * ND;
    int n = loc / DD, d = loc - n * DD;
    const int* xs = gi ? x1 : x0;
    int a = xs[2 * n], c = xs[2 * n + 1];
    g_h[idx] = xemb1[a * DD + d] + xemb2[c * DD + d];
}

// ---------------- per-layer per-graph kernels --------------------------------

// stats -> scale/shift table; re-zero stats (one graph)
__global__ void k_bnprep(int gi,
                         const float* __restrict__ gamma_l,
                         const float* __restrict__ beta_l) {
    int d = blockIdx.x * blockDim.x + threadIdx.x;
    if (d >= DD) return;
    int idx = gi * DD + d;
    float s = g_sum[idx];
    float q = g_sumsq[idx];
    float mu = s * (1.0f / NN);
    float var = q * (1.0f / NN) - mu * mu;
    float rstd = rsqrtf(var + 1e-5f);
    float sc = rstd * gamma_l[d];
    g_scale[idx] = sc;
    g_shift[idx] = beta_l[d] - mu * sc;
    g_sum[idx] = 0.f;
    g_sumsq[idx] = 0.f;
}

// CSR aggregate (one graph), BN-on-read for l>0, bf16 split store
__global__ void k_aggregate(int l, int gi,
                            const float* __restrict__ e1l,
                            const float* __restrict__ e2l) {
    int idx = blockIdx.x * blockDim.x + threadIdx.x;
    const int TPG = NN * 75;
    if (idx >= TPG) return;
    int n = idx / 75, dq = idx - n * 75;
    int d = dq * 4;
    const float* src = (l == 0) ? (g_h + (size_t)gi * ND) : (g_h2 + (size_t)gi * ND);

    float4 scale, shift;
    if (l == 0) {
        scale = make_float4(1.f, 1.f, 1.f, 1.f);
        shift = make_float4(0.f, 0.f, 0.f, 0.f);
    } else {
        scale = *(const float4*)&g_scale[gi * DD + d];
        shift = *(const float4*)&g_shift[gi * DD + d];
    }

    auto ldsrc = [&](int node) -> float4 {
        float4 r = *(const float4*)&src[(size_t)node * DD + d];
        if (l > 0) {
            r.x = fmaxf(fmaf(r.x, scale.x, shift.x), 0.f);
            r.y = fmaxf(fmaf(r.y, scale.y, shift.y), 0.f);
            r.z = fmaxf(fmaf(r.z, scale.z, shift.z), 0.f);
            r.w = fmaxf(fmaf(r.w, scale.w, shift.w), 0.f);
        }
        return r;
    };

    float4 v = ldsrc(n);
    float4 s1 = *(const float4*)&e1l[4 * DD + d];
    float4 s2 = *(const float4*)&e2l[d];
    v.x += s1.x + s2.x; v.y += s1.y + s2.y;
    v.z += s1.z + s2.z; v.w += s1.w + s2.w;

    int beg = g_off[gi * (NN + 1) + n];
    int end = g_off[gi * (NN + 1) + n + 1];
    const int* el = g_elist + gi * NE;
    for (int j = beg; j < end; j++) {
        int p = el[j];
        int srcn = p & 0x1FFFF;
        int c = p >> 17;
        int a0 = c / 3, a1 = c - a0 * 3;
        float4 hv = ldsrc(srcn);
        float4 t1 = *(const float4*)&e1l[a0 * DD + d];
        float4 t2 = *(const float4*)&e2l[a1 * DD + d];
        v.x += hv.x + t1.x + t2.x;
        v.y += hv.y + t1.y + t2.y;
        v.z += hv.z + t1.z + t2.z;
        v.w += hv.w + t1.w + t2.w;
    }

    union { __nv_bfloat162 b2[2]; uint2 u; } uh, ul;
    __nv_bfloat16 h0 = __float2bfloat16(v.x), h1 = __float2bfloat16(v.y);
    __nv_bfloat16 h2 = __float2bfloat16(v.z), h3 = __float2bfloat16(v.w);
    uh.b2[0].x = h0; uh.b2[0].y = h1; uh.b2[1].x = h2; uh.b2[1].y = h3;
    ul.b2[0].x = __float2bfloat16(v.x - __bfloat162float(h0));
    ul.b2[0].y = __float2bfloat16(v.y - __bfloat162float(h1));
    ul.b2[1].x = __float2bfloat16(v.z - __bfloat162float(h2));
    ul.b2[1].y = __float2bfloat16(v.w - __bfloat162float(h3));
    size_t m = (size_t)(gi * MPAD + n);
    *(uint2*)&g_Ahi[m * K1P + d] = uh.u;
    *(uint2*)&g_Alo[m * K1P + d] = ul.u;
}

// ---------------- mma.sync bf16-split GEMM (per graph) -----------------------
template <int TN, int MODE>
__global__ void __launch_bounds__(256)
k_mgemm(int l, int gi, const float* __restrict__ bias, int colbase) {
    constexpr int KPAD = MODE ? K2P : K1P;
    constexpr int NC   = MODE ? DD  : DD2;
    constexpr int NCHUNK = KPAD / 32;
    constexpr int JT = TN / 32;
    constexpr int BMATB = TN * RS;
    constexpr int STAGEB = 2 * MATB + 2 * BMATB;
    const __nv_bfloat16* __restrict__ Ahi = MODE ? g_Thi : g_Ahi;
    const __nv_bfloat16* __restrict__ Alo = MODE ? g_Tlo : g_Alo;
    const __nv_bfloat16* __restrict__ Bhi =
        MODE ? (g_W2hi + (size_t)l * N2P * K2P) : (g_W1hi + (size_t)l * N1P * K1P);
    const __nv_bfloat16* __restrict__ Blo =
        MODE ? (g_W2lo + (size_t)l * N2P * K2P) : (g_W1lo + (size_t)l * N1P * K1P);

    extern __shared__ __align__(16) char smem[];
    const uint32_t sbase = smem_to_u32(smem);
    const int tid = threadIdx.x;
    const int wid = tid >> 5;
    const int lane = tid & 31;
    const int row0 = gi * MPAD + blockIdx.y * 128;
    const int col0 = colbase + blockIdx.x * TN;
    const int wm = wid & 1;
    const int wn = wid >> 1;
    const int lr = lane & 15;
    const int lc = lane >> 4;

    auto issue = [&](int c) {
        const int buf = c & 1;
        const int k0 = c * 32;
        #pragma unroll
        for (int i = 0; i < 4; i++) {
            int u = tid + i * 256;
            int mat = u >> 9;
            int r = (u >> 2) & 127;
            int c16 = u & 3;
            const __nv_bfloat16* gp = (mat ? Alo : Ahi)
                + (size_t)(row0 + r) * KPAD + k0 + c16 * 8;
            uint32_t dst = sbase + buf * STAGEB + mat * MATB + r * RS + c16 * 16;
            CP_ASYNC16(dst, gp);
        }
        #pragma unroll
        for (int i = 0; i < TN / 32; i++) {
            int u = tid + i * 256;
            int mat = u / (4 * TN);
            int w = u - mat * (4 * TN);
            int r = w >> 2;
            int c16 = w & 3;
            const __nv_bfloat16* gp = (mat ? Blo : Bhi)
                + (size_t)(col0 + r) * KPAD + k0 + c16 * 8;
            uint32_t dst = sbase + buf * STAGEB + 2 * MATB + mat * BMATB
                         + r * RS + c16 * 16;
            CP_ASYNC16(dst, gp);
        }
        CP_COMMIT();
    };

    float acc[4][JT][4] = {};

    issue(0);
    for (int c = 0; c < NCHUNK; c++) {
        if (c + 1 < NCHUNK) { issue(c + 1); CP_WAIT1(); }
        else                { CP_WAIT0(); }
        __syncthreads();
        const uint32_t sb = sbase + (c & 1) * STAGEB;
        #pragma unroll
        for (int s = 0; s < 2; s++) {
            uint32_t ahi[4][4], alo[4][4], bhi[JT][2], blo[JT][2];
            #pragma unroll
            for (int i = 0; i < 4; i++) {
                uint32_t ra = sb + (wm * 64 + i * 16 + lr) * RS + s * 32 + lc * 16;
                LDMX4(ahi[i], ra);
                LDMX4(alo[i], ra + MATB);
            }
            #pragma unroll
            for (int jp = 0; jp < JT / 2; jp++) {
                uint32_t rb = sb + 2 * MATB + (wn * (TN / 4) + jp * 16 + lr) * RS
                            + s * 32 + lc * 16;
                uint32_t t[4];
                LDMX4(t, rb);
                bhi[2 * jp][0] = t[0]; bhi[2 * jp + 1][0] = t[1];
                bhi[2 * jp][1] = t[2]; bhi[2 * jp + 1][1] = t[3];
                LDMX4(t, rb + BMATB);
                blo[2 * jp][0] = t[0]; blo[2 * jp + 1][0] = t[1];
                blo[2 * jp][1] = t[2]; blo[2 * jp + 1][1] = t[3];
            }
            #pragma unroll
            for (int i = 0; i < 4; i++)
                #pragma unroll
                for (int j = 0; j < JT; j++) {
                    MMA_BF16(acc[i][j], ahi[i], bhi[j]);
                    MMA_BF16(acc[i][j], ahi[i], blo[j]);
                    MMA_BF16(acc[i][j], alo[i], bhi[j]);
                }
        }
        __syncthreads();
    }

    if (MODE == 0) {
        #pragma unroll
        for (int i = 0; i < 4; i++) {
            #pragma unroll
            for (int j = 0; j < JT; j++) {
                #pragma unroll
                for (int h = 0; h < 2; h++) {
                    int m = row0 + wm * 64 + i * 16 + (lane >> 2) + h * 8;
                    int n = col0 + wn * (TN / 4) + j * 8 + (lane & 3) * 2;
                    if (n >= K2P) continue;
                    float v0 = acc[i][j][h * 2];
                    float v1 = acc[i][j][h * 2 + 1];
                    if (n < NC) {
                        v0 = fmaxf(v0 + bias[n], 0.f);
                        v1 = fmaxf(v1 + bias[n + 1], 0.f);
                    } else { v0 = 0.f; v1 = 0.f; }
                    __nv_bfloat16 h0 = __float2bfloat16(v0);
                    __nv_bfloat16 h1 = __float2bfloat16(v1);
                    __nv_bfloat16 l0 = __float2bfloat16(v0 - __bfloat162float(h0));
                    __nv_bfloat16 l1 = __float2bfloat16(v1 - __bfloat162float(h1));
                    size_t o = (size_t)m * K2P + n;
                    __nv_bfloat162 th; th.x = h0; th.y = h1;
                    __nv_bfloat162 tl; tl.x = l0; tl.y = l1;
                    *(__nv_bfloat162*)&g_Thi[o] = th;
                    *(__nv_bfloat162*)&g_Tlo[o] = tl;
                }
            }
        }
    } else {
        const int sb2 = gi * DD;
        float cs[2 * JT], cq[2 * JT];
        #pragma unroll
        for (int k = 0; k < 2 * JT; k++) { cs[k] = 0.f; cq[k] = 0.f; }
        #pragma unroll
        for (int i = 0; i < 4; i++) {
            #pragma unroll
            for (int j = 0; j < JT; j++) {
                #pragma unroll
                for (int h = 0; h < 2; h++) {
                    int m = row0 + wm * 64 + i * 16 + (lane >> 2) + h * 8;
                    int node = m - gi * MPAD;
                    int n = col0 + wn * (TN / 4) + j * 8 + (lane & 3) * 2;
                    if (node < NN && n < NC) {
                        float v0 = acc[i][j][h * 2]     + bias[n];
                        float v1 = acc[i][j][h * 2 + 1] + bias[n + 1];
                        float2 v; v.x = v0; v.y = v1;
                        *(float2*)&g_h2[((size_t)gi * NN + node) * DD + n] = v;
                        cs[j * 2]     += v0; cq[j * 2]     += v0 * v0;
                        cs[j * 2 + 1] += v1; cq[j * 2 + 1] += v1 * v1;
                    }
                }
            }
        }
        #pragma unroll
        for (int off = 4; off < 32; off <<= 1) {
            #pragma unroll
            for (int k = 0; k < 2 * JT; k++) {
                cs[k] += __shfl_xor_sync(0xffffffffu, cs[k], off);
                cq[k] += __shfl_xor_sync(0xffffffffu, cq[k], off);
            }
        }
        if ((lane >> 2) == 0) {
            #pragma unroll
            for (int k = 0; k < 2 * JT; k++) {
                int n = col0 + wn * (TN / 4) + (k >> 1) * 8 + (lane & 3) * 2 + (k & 1);
                if (n < NC) {
                    atomicAdd(&g_sum[sb2 + n], cs[k]);
                    atomicAdd(&g_sumsq[sb2 + n], cq[k]);
                }
            }
        }
    }
}

#define SMEM_128 (2 * (2 * MATB + 2 * 128 * RS))   // 81920
#define SMEM_64  (2 * (2 * MATB + 2 * 64 * RS))    // 61440

// ---------------- final BN + pool + pred (per graph) -------------------------

__global__ void k_bnpool(int gi, const int* __restrict__ batch,
                         float* __restrict__ nrep) {
    int idx = blockIdx.x * blockDim.x + threadIdx.x;
    if (idx >= ND) return;
    int n = idx / DD, d = idx % DD;
    float v = fmaf(g_h2[(size_t)gi * ND + idx],
                   g_scale[gi * DD + d], g_shift[gi * DD + d]);
    nrep[idx] = v;
    int b = batch[n];
    atomicAdd(&g_gsum[((size_t)gi * NG + b) * DD + d], v);
    if (d == 0) atomicAdd(&g_gcnt[gi * NG + b], 1.0f);
}

__global__ void k_pred(int gi,
                       const float* __restrict__ predW,
                       const float* __restrict__ predb,
                       float* __restrict__ grep, float* __restrict__ pred) {
    int g = blockIdx.x;
    __shared__ float rep[DD];
    float inv = 1.0f / fmaxf(g_gcnt[gi * NG + g], 1.0f);
    for (int d = threadIdx.x; d < DD; d += blockDim.x) {
        float v = g_gsum[((size_t)gi * NG + g) * DD + d] * inv;
        rep[d] = v;
        grep[g * DD + d] = v;
    }
    __syncthreads();
    if (threadIdx.x < NT) {
        int t = threadIdx.x;
        float acc = predb[t];
        for (int d = 0; d < DD; ++d) acc += rep[d] * predW[d * NT + t];
        pred[g * NT + t] = acc;
    }
}

// ---------------- host orchestration (dual-stream fork/join) -----------------

extern "C" void kernel_launch(void* const* d_in, const int* in_sizes, int n_in,
                              void* d_out, int out_size) {
    const int*   x      = (const int*)d_in[0];
    const int*   ei     = (const int*)d_in[1];
    const int*   ea     = (const int*)d_in[2];
    const int*   batch  = (const int*)d_in[3];
    const int*   x1     = (const int*)d_in[4];
    const int*   ei1    = (const int*)d_in[5];
    const int*   ea1    = (const int*)d_in[6];
    const int*   batch1 = (const int*)d_in[7];
    const float* xemb1  = (const float*)d_in[8];
    const float* xemb2  = (const float*)d_in[9];
    const float* eemb1  = (const float*)d_in[10];
    const float* eemb2  = (const float*)d_in[11];
    const float* W1     = (const float*)d_in[12];
    const float* b1     = (const float*)d_in[13];
    const float* W2     = (const float*)d_in[14];
    const float* b2     = (const float*)d_in[15];
    const float* gamma  = (const float*)d_in[16];
    const float* beta   = (const float*)d_in[17];
    const float* predW  = (const float*)d_in[18];
    const float* predb  = (const float*)d_in[19];

    static cudaStream_t s_gr[2] = {nullptr, nullptr};
    static cudaEvent_t ev_fork = nullptr, ev_join0 = nullptr, ev_join1 = nullptr;
    if (!s_gr[0]) {
        cudaStreamCreateWithFlags(&s_gr[0], cudaStreamNonBlocking);
        cudaStreamCreateWithFlags(&s_gr[1], cudaStreamNonBlocking);
        cudaEventCreateWithFlags(&ev_fork, cudaEventDisableTiming);
        cudaEventCreateWithFlags(&ev_join0, cudaEventDisableTiming);
        cudaEventCreateWithFlags(&ev_join1, cudaEventDisableTiming);
        cudaFuncSetAttribute((const void*)k_mgemm<128, 0>,
                             cudaFuncAttributeMaxDynamicSharedMemorySize, SMEM_128);
        cudaFuncSetAttribute((const void*)k_mgemm<128, 1>,
                             cudaFuncAttributeMaxDynamicSharedMemorySize, SMEM_128);
        cudaFuncSetAttribute((const void*)k_mgemm<64, 1>,
                             cudaFuncAttributeMaxDynamicSharedMemorySize, SMEM_64);
    }

    float* out = (float*)d_out;
    float* pred0 = out;
    float* grep0 = out + NG * NT;
    float* nrep0 = out + NG * NT + NG * DD;
    float* pred1 = out + NG * NT + NG * DD + (size_t)NN * DD;
    float* grep1 = pred1 + NG * NT;
    float* nrep1 = pred1 + NG * NT + NG * DD;
    float* npr[2] = {nrep0, nrep1};
    float* grp[2] = {grep0, grep1};
    float* prd[2] = {pred0, pred1};
    const int* bat[2] = {batch, batch1};

    const int BLK = 256;
    const int GRID_2ND = (2 * ND + BLK - 1) / BLK;
    const int GRID_ND1 = (ND + BLK - 1) / BLK;
    const int GRID_2NE = (2 * NE + BLK - 1) / BLK;
    const int GRID_M = MPAD / 128;  // 391 per graph
    const int GRID_AGG = (NN * 75 + BLK - 1) / BLK;
    const int GRID_ZP = (2 * ZR1 + 2 * ZR2 + BLK - 1) / BLK;

    // one-time builds on the default stream
    k_split_w<<<(W1TOT + W2TOT + 255) / 256, 256>>>(W1, W2);
    k_count<<<GRID_2NE, BLK>>>(ei, ei1);
    k_scan<<<2, 1024>>>();
    k_fill<<<GRID_2NE, BLK>>>(ei, ea, ei1, ea1);
    k_zero_pad<<<GRID_ZP, BLK>>>();
    k_init<<<GRID_2ND, BLK>>>(x, x1, xemb1, xemb2);

    // fork
    cudaEventRecord(ev_fork, 0);
    cudaStreamWaitEvent(s_gr[0], ev_fork, 0);
    cudaStreamWaitEvent(s_gr[1], ev_fork, 0);

    for (int gi = 0; gi < 2; gi++) {
        cudaStream_t s = s_gr[gi];
        for (int l = 0; l < NL; ++l) {
            const float* e1l = eemb1 + (size_t)l * NUM_BOND * DD;
            const float* e2l = eemb2 + (size_t)l * NUM_DIR * DD;
            if (l > 0)
                k_bnprep<<<2, 256, 0, s>>>(gi, gamma + (size_t)(l - 1) * DD,
                                           beta + (size_t)(l - 1) * DD);
            k_aggregate<<<GRID_AGG, BLK, 0, s>>>(l, gi, e1l, e2l);
            k_mgemm<128, 0><<<dim3(N1P / 128, GRID_M), 256, SMEM_128, s>>>(
                l, gi, b1 + (size_t)l * DD2, 0);
            k_mgemm<128, 1><<<dim3(2, GRID_M), 256, SMEM_128, s>>>(
                l, gi, b2 + (size_t)l * DD, 0);
            k_mgemm<64, 1><<<dim3(1, GRID_M), 256, SMEM_64, s>>>(
                l, gi, b2 + (size_t)l * DD, 256);
        }
        k_bnprep<<<2, 256, 0, s>>>(gi, gamma + (size_t)(NL - 1) * DD,
                                   beta + (size_t)(NL - 1) * DD);
        k_bnpool<<<GRID_ND1, BLK, 0, s>>>(gi, bat[gi], npr[gi]);
        k_pred<<<NG, 128, 0, s>>>(gi, predW, predb, grp[gi], prd[gi]);
    }

    // join
    cudaEventRecord(ev_join0, s_gr[0]);
    cudaEventRecord(ev_join1, s_gr[1]);
    cudaStreamWaitEvent(0, ev_join0, 0);
    cudaStreamWaitEvent(0, ev_join1, 0);
}